// round 14
// baseline (speedup 1.0000x reference)
#include <cuda_runtime.h>
#include <math.h>

#define L 2048
#define TOKS 512
#define CA 128
#define CP 16
#define CT 384
#define NH 4
#define HD 32
#define FFDIM 512
#define NBLK 3
#define F1D 388
#define KSPLIT 32

#define OFF_A 0
#define OFF_Q (TOKS*CT)
#define OFF_CL (OFF_Q + L*CA)
#define OFF_P (OFF_CL + L*CA)

typedef unsigned long long u64;

// ---------------- f32x2 helpers ----------------
__device__ __forceinline__ u64 pack2(float lo, float hi) {
    u64 r; asm("mov.b64 %0, {%1, %2};" : "=l"(r) : "f"(lo), "f"(hi)); return r;
}
__device__ __forceinline__ void unpack2(u64 v, float& lo, float& hi) {
    asm("mov.b64 {%0, %1}, %2;" : "=f"(lo), "=f"(hi) : "l"(v));
}
__device__ __forceinline__ u64 fma2(u64 a, u64 b, u64 c) {
    u64 d; asm("fma.rn.f32x2 %0, %1, %2, %3;" : "=l"(d) : "l"(a), "l"(b), "l"(c)); return d;
}
__device__ __forceinline__ u64 mul2(u64 a, u64 b) {
    u64 d; asm("mul.rn.f32x2 %0, %1, %2;" : "=l"(d) : "l"(a), "l"(b)); return d;
}
__device__ __forceinline__ u64 add2(u64 a, u64 b) {
    u64 d; asm("add.rn.f32x2 %0, %1, %2;" : "=l"(d) : "l"(a), "l"(b)); return d;
}
__device__ __forceinline__ u64 relu2(u64 v) {
    float lo, hi; unpack2(v, lo, hi);
    return pack2(fmaxf(lo, 0.f), fmaxf(hi, 0.f));
}

// ---------------- scratch ----------------
__device__ float g_Q  [L*CA];
__device__ float g_qm [L*CA];
__device__ float g_km [L*CA];
__device__ float g_vm [L*CA];
__device__ float g_ff [L*FFDIM];
__device__ float g_sl [L*CP];
__device__ float g_sm [L*CP];
__device__ float g_bias[(size_t)NBLK*NH*L*L];           // [b][h][l][m]
__device__ float g_pmax[KSPLIT*L*NH];
__device__ float g_psum[KSPLIT*L*NH];
__device__ float g_pacc[(size_t)KSPLIT*L*NH*HD];

// ---------------- C_L = concat(feat)@W_in ; seeds Q ; fused sl/sm projections ----------------
__global__ void k_cl(const float* __restrict__ pos, const float* __restrict__ charge,
                     const float* __restrict__ elem, const float* __restrict__ chars,
                     const float* __restrict__ Win, const float* __restrict__ Wsl,
                     const float* __restrict__ Wsm, float* __restrict__ outCL)
{
    __shared__ float f[F1D];
    __shared__ float r[128];
    int l = blockIdx.x, t = threadIdx.x;
    if (t < 3)  f[t]   = pos[l*3 + t];
    if (t == 3) f[3]   = charge[l];
    f[4   + t] = elem [l*128 + t];
    f[132 + t] = chars[l*256 + t];
    f[260 + t] = chars[l*256 + 128 + t];
    __syncthreads();
    float acc = 0.f;
    #pragma unroll 4
    for (int k = 0; k < F1D; k++) acc += f[k] * Win[(size_t)k*CA + t];
    outCL[(size_t)l*CA + t] = acc;
    g_Q  [(size_t)l*CA + t] = acc;
    r[t] = fmaxf(acc, 0.f);
    __syncthreads();
    if (t < 16) {
        float a = 0.f;
        #pragma unroll 4
        for (int k = 0; k < 128; k++) a += r[k] * Wsl[k*16 + t];
        g_sl[l*16 + t] = a;
    } else if (t < 32) {
        int c = t - 16;
        float a = 0.f;
        #pragma unroll 4
        for (int k = 0; k < 128; k++) a += r[k] * Wsm[k*16 + c];
        g_sm[l*16 + c] = a;
    }
}

// ---------------- pair v3: 4 atoms/thread (two atom-pairs), dup weights, LDS amortized ----------------
__global__ void __launch_bounds__(128, 2)
k_pair(const float* __restrict__ pos, const int* __restrict__ uid,
       const float* __restrict__ Wd,  const float* __restrict__ Wiv,
       const float* __restrict__ Wvm, const float* __restrict__ Wp1,
       const float* __restrict__ Wp2, const float* __restrict__ Wp3,
       const float* __restrict__ Wb,  float* __restrict__ outP)
{
    __shared__ u64 wd2[48], wiv2[16], wvm2[16], w1[256], w2[256], w3[256], wb2[192], sl2[16];
    __shared__ float pl[3];
    __shared__ int ul;
    int l = blockIdx.y;
    int t = threadIdx.x;
    int m0 = blockIdx.x*512 + t;       // atoms m0, m0+128, m0+256, m0+384

    for (int i = t; i < 256; i += 128) {
        w1[i] = pack2(Wp1[i], Wp1[i]);
        w2[i] = pack2(Wp2[i], Wp2[i]);
        w3[i] = pack2(Wp3[i], Wp3[i]);
    }
    for (int i = t; i < 192; i += 128) wb2[i] = pack2(Wb[i], Wb[i]);
    if (t < 48) wd2[t] = pack2(Wd[t], Wd[t]);
    if (t < 16) {
        wiv2[t] = pack2(Wiv[t], Wiv[t]);
        wvm2[t] = pack2(Wvm[t], Wvm[t]);
        float s = g_sl[l*16 + t];
        sl2[t]  = pack2(s, s);
    }
    if (t < 3)  pl[t] = pos[l*3 + t];
    if (t == 0) ul = uid[l];
    __syncthreads();

    // geometry: pair k covers atoms (m0+k*256, m0+k*256+128), packed (lo,hi)
    u64 d0p[2], d1p[2], d2p[2], ivp[2], vfp[2];
    #pragma unroll
    for (int k = 0; k < 2; k++) {
        int ma = m0 + k*256, mb = ma + 128;
        float ax = pl[0]-pos[ma*3+0], ay = pl[1]-pos[ma*3+1], az = pl[2]-pos[ma*3+2];
        float bx = pl[0]-pos[mb*3+0], by = pl[1]-pos[mb*3+1], bz = pl[2]-pos[mb*3+2];
        float iva = 1.f/(1.f+sqrtf(ax*ax+ay*ay+az*az));
        float ivb = 1.f/(1.f+sqrtf(bx*bx+by*by+bz*bz));
        float vfa = (ul==uid[ma]) ? 1.f : 0.f;
        float vfb = (ul==uid[mb]) ? 1.f : 0.f;
        d0p[k]=pack2(ax,bx); d1p[k]=pack2(ay,by); d2p[k]=pack2(az,bz);
        ivp[k]=pack2(iva,ivb); vfp[k]=pack2(vfa,vfb);
    }

    // p init per channel (weights LDS shared across both pairs)
    u64 p0[16], p1[16];
    {
        const float4* s0 = (const float4*)(g_sm + (size_t)m0*16);
        const float4* s1 = (const float4*)(g_sm + (size_t)(m0+128)*16);
        const float4* s2 = (const float4*)(g_sm + (size_t)(m0+256)*16);
        const float4* s3 = (const float4*)(g_sm + (size_t)(m0+384)*16);
        #pragma unroll
        for (int i = 0; i < 4; i++) {
            float4 va = s0[i], vb = s1[i], vc = s2[i], vd = s3[i];
            u64 smA[4] = {pack2(va.x,vb.x), pack2(va.y,vb.y), pack2(va.z,vb.z), pack2(va.w,vb.w)};
            u64 smB[4] = {pack2(vc.x,vd.x), pack2(vc.y,vd.y), pack2(vc.z,vd.z), pack2(vc.w,vd.w)};
            #pragma unroll
            for (int q = 0; q < 4; q++) {
                int c = 4*i + q;
                u64 wdc0=wd2[c], wdc1=wd2[16+c], wdc2=wd2[32+c];
                u64 wivc=wiv2[c], wvmc=wvm2[c], slc=sl2[c];
                u64 t0 = wvmc;
                t0 = fma2(ivp[0], wivc, t0);
                t0 = fma2(d2p[0], wdc2, t0);
                t0 = fma2(d1p[0], wdc1, t0);
                t0 = fma2(d0p[0], wdc0, t0);
                p0[c] = fma2(vfp[0], t0, add2(slc, smA[q]));
                u64 t1 = wvmc;
                t1 = fma2(ivp[1], wivc, t1);
                t1 = fma2(d2p[1], wdc2, t1);
                t1 = fma2(d1p[1], wdc1, t1);
                t1 = fma2(d0p[1], wdc0, t1);
                p1[c] = fma2(vfp[1], t1, add2(slc, smB[q]));
            }
        }
    }

    u64 r0[16], r1[16], a0[16], a1[16];

    // layer 1
    #pragma unroll
    for (int c = 0; c < 16; c++) { r0[c]=relu2(p0[c]); r1[c]=relu2(p1[c]); a0[c]=0ull; a1[c]=0ull; }
    #pragma unroll 1
    for (int j = 0; j < 16; j++) {
        u64 rj0 = r0[j], rj1 = r1[j];
        #pragma unroll
        for (int c = 0; c < 16; c++) {
            u64 w = w1[j*16 + c];
            a0[c] = fma2(rj0, w, a0[c]);
            a1[c] = fma2(rj1, w, a1[c]);
        }
    }
    // layer 2
    #pragma unroll
    for (int c = 0; c < 16; c++) { r0[c]=relu2(a0[c]); r1[c]=relu2(a1[c]); a0[c]=0ull; a1[c]=0ull; }
    #pragma unroll 1
    for (int j = 0; j < 16; j++) {
        u64 rj0 = r0[j], rj1 = r1[j];
        #pragma unroll
        for (int c = 0; c < 16; c++) {
            u64 w = w2[j*16 + c];
            a0[c] = fma2(rj0, w, a0[c]);
            a1[c] = fma2(rj1, w, a1[c]);
        }
    }
    // layer 3 + residual
    #pragma unroll
    for (int c = 0; c < 16; c++) { r0[c]=relu2(a0[c]); r1[c]=relu2(a1[c]); a0[c]=0ull; a1[c]=0ull; }
    #pragma unroll 1
    for (int j = 0; j < 16; j++) {
        u64 rj0 = r0[j], rj1 = r1[j];
        #pragma unroll
        for (int c = 0; c < 16; c++) {
            u64 w = w3[j*16 + c];
            a0[c] = fma2(rj0, w, a0[c]);
            a1[c] = fma2(rj1, w, a1[c]);
        }
    }
    #pragma unroll
    for (int c = 0; c < 16; c++) { p0[c]=add2(p0[c],a0[c]); p1[c]=add2(p1[c],a1[c]); }

    // store P: 4 atom rows
    {
        float lo[16], hi[16];
        #pragma unroll
        for (int c = 0; c < 16; c++) unpack2(p0[c], lo[c], hi[c]);
        float4* da = (float4*)(outP + ((size_t)l*L + m0)*16);
        float4* db = (float4*)(outP + ((size_t)l*L + m0+128)*16);
        #pragma unroll
        for (int i = 0; i < 4; i++) {
            da[i] = make_float4(lo[4*i], lo[4*i+1], lo[4*i+2], lo[4*i+3]);
            db[i] = make_float4(hi[4*i], hi[4*i+1], hi[4*i+2], hi[4*i+3]);
        }
        #pragma unroll
        for (int c = 0; c < 16; c++) unpack2(p1[c], lo[c], hi[c]);
        float4* dc = (float4*)(outP + ((size_t)l*L + m0+256)*16);
        float4* dd = (float4*)(outP + ((size_t)l*L + m0+384)*16);
        #pragma unroll
        for (int i = 0; i < 4; i++) {
            dc[i] = make_float4(lo[4*i], lo[4*i+1], lo[4*i+2], lo[4*i+3]);
            dd[i] = make_float4(hi[4*i], hi[4*i+1], hi[4*i+2], hi[4*i+3]);
        }
    }

    // bias: 12 outputs (3 blocks x 4 heads), LDS shared across both pairs
    u64 b0[12], b1[12];
    #pragma unroll
    for (int o = 0; o < 12; o++) { b0[o]=0ull; b1[o]=0ull; }
    #pragma unroll 1
    for (int c = 0; c < 16; c++) {
        u64 pc0 = p0[c], pc1 = p1[c];
        #pragma unroll
        for (int o = 0; o < 12; o++) {
            int bb = o >> 2, h = o & 3;
            u64 w = wb2[bb*64 + c*4 + h];
            b0[o] = fma2(pc0, w, b0[o]);
            b1[o] = fma2(pc1, w, b1[o]);
        }
    }
    #pragma unroll
    for (int o = 0; o < 12; o++) {
        int bb = o >> 2, h = o & 3;
        float* base = g_bias + ((size_t)(bb*NH + h)*L + l)*L;
        float x0, x1, x2, x3;
        unpack2(b0[o], x0, x1);
        unpack2(b1[o], x2, x3);
        base[m0]     = x0;
        base[m0+128] = x1;
        base[m0+256] = x2;
        base[m0+384] = x3;
    }
}

// ---------------- fused QKV (LN + 3 gemms), R=16 rows/CTA ----------------
__global__ void __launch_bounds__(256)
k_qkv(const float* __restrict__ X, const float* __restrict__ Wq,
      const float* __restrict__ Wk, const float* __restrict__ Wv)
{
    const float* W = (blockIdx.y == 0) ? Wq : (blockIdx.y == 1) ? Wk : Wv;
    float* O = (blockIdx.y == 0) ? g_qm : (blockIdx.y == 1) ? g_km : g_vm;

    constexpr int R = 16;
    __shared__ u64 xs2[R*128];
    int r0 = blockIdx.x * R;
    int t  = threadIdx.x;

    {
        int r  = t >> 4, c0 = t & 15;
        const float* xr = X + (size_t)(r0 + r)*128;
        float v[8]; float s = 0.f, ss = 0.f;
        #pragma unroll
        for (int i = 0; i < 8; i++) { v[i] = xr[c0 + i*16]; s += v[i]; ss += v[i]*v[i]; }
        #pragma unroll
        for (int o = 8; o >= 1; o >>= 1) {
            s  += __shfl_xor_sync(0xffffffffu, s,  o);
            ss += __shfl_xor_sync(0xffffffffu, ss, o);
        }
        float mu   = s * (1.f/128.f);
        float rstd = rsqrtf(ss * (1.f/128.f) - mu*mu + 1e-5f);
        #pragma unroll
        for (int i = 0; i < 8; i++) {
            float nv = (v[i] - mu) * rstd;
            xs2[r*128 + c0 + i*16] = pack2(nv, nv);
        }
    }
    __syncthreads();

    int cp = t & 63;
    int g  = t >> 6;
    const u64* Wp = (const u64*)W + cp;
    u64 acc[4] = {0ull, 0ull, 0ull, 0ull};
    #pragma unroll 4
    for (int k = 0; k < 128; k++) {
        u64 w2 = Wp[(size_t)k*64];
        #pragma unroll
        for (int r = 0; r < 4; r++)
            acc[r] = fma2(xs2[(g*4 + r)*128 + k], w2, acc[r]);
    }
    #pragma unroll
    for (int r = 0; r < 4; r++) {
        float lo, hi; unpack2(acc[r], lo, hi);
        float* o = O + (size_t)(r0 + g*4 + r)*128 + 2*cp;
        o[0] = lo; o[1] = hi;
    }
}

// ---------------- attention v3b: 2 queries/thread, reg cap 170 for 3 CTAs/SM ----------------
__global__ void __launch_bounds__(128, 3) k_attn_split(int b)
{
    const float L2E = 1.4426950408889634f;
    const float SCALE_L2E = 0.1767766952966369f * L2E;

    int h  = blockIdx.y;
    int s  = blockIdx.z;
    int q0 = blockIdx.x * 256;
    int t  = threadIdx.x;
    int qa = q0 + t;
    int qb = qa + 128;

    __shared__ alignas(16) float ks[32*32];
    __shared__ alignas(16) float vs[32*32];
    __shared__ float bs[256*33];

    u64 qA[16], qB[16];
    {
        u64 sc2 = pack2(SCALE_L2E, SCALE_L2E);
        const ulonglong2* pa = (const ulonglong2*)(g_qm + (size_t)qa*CA + h*HD);
        const ulonglong2* pb = (const ulonglong2*)(g_qm + (size_t)qb*CA + h*HD);
        #pragma unroll
        for (int i = 0; i < 8; i++) {
            ulonglong2 va = pa[i], vb = pb[i];
            qA[2*i] = mul2(va.x, sc2); qA[2*i+1] = mul2(va.y, sc2);
            qB[2*i] = mul2(vb.x, sc2); qB[2*i+1] = mul2(vb.y, sc2);
        }
    }

    float rmaxA = -1e30f, rmaxB = -1e30f, ssumA = 0.f, ssumB = 0.f;
    u64 accA[16], accB[16];
    #pragma unroll
    for (int i = 0; i < 16; i++) { accA[i] = 0ull; accB[i] = 0ull; }

    const float* bsrc_base = g_bias + ((size_t)(b*NH + h)*L + q0)*L;
    int m_begin = s * (L/KSPLIT);
    int m_end   = m_begin + (L/KSPLIT);

    for (int m0 = m_begin; m0 < m_end; m0 += 32) {
        __syncthreads();
        for (int i = t; i < 256; i += 128) {
            int j = i >> 3, dq = i & 7;
            ((float4*)ks)[i] = ((const float4*)g_km)[(size_t)(m0+j)*32 + h*8 + dq];
            ((float4*)vs)[i] = ((const float4*)g_vm)[(size_t)(m0+j)*32 + h*8 + dq];
        }
        for (int i = t; i < 2048; i += 128) {
            int t2 = i >> 3, jv = i & 7;
            float4 v = *(const float4*)(bsrc_base + (size_t)t2*L + m0 + jv*4);
            float* d = bs + t2*33 + jv*4;
            d[0] = v.x*L2E; d[1] = v.y*L2E; d[2] = v.z*L2E; d[3] = v.w*L2E;
        }
        __syncthreads();

        float tmaxA = -1e30f, tmaxB = -1e30f;
        #pragma unroll 2
        for (int j = 0; j < 32; j++) {
            const ulonglong2* k2 = (const ulonglong2*)(ks + j*32);
            u64 dA0 = pack2(bs[t*33 + j], 0.f);
            u64 dA1 = 0ull;
            u64 dB0 = pack2(bs[(t+128)*33 + j], 0.f);
            u64 dB1 = 0ull;
            #pragma unroll
            for (int i = 0; i < 8; i++) {
                ulonglong2 kk = k2[i];
                dA0 = fma2(qA[2*i],   kk.x, dA0);
                dA1 = fma2(qA[2*i+1], kk.y, dA1);
                dB0 = fma2(qB[2*i],   kk.x, dB0);
                dB1 = fma2(qB[2*i+1], kk.y, dB1);
            }
            u64 dA = add2(dA0, dA1);
            u64 dB = add2(dB0, dB1);
            float a_lo, a_hi, b_lo, b_hi;
            unpack2(dA, a_lo, a_hi);
            unpack2(dB, b_lo, b_hi);
            float la = a_lo + a_hi, lb = b_lo + b_hi;
            bs[t*33 + j]       = la;
            bs[(t+128)*33 + j] = lb;
            tmaxA = fmaxf(tmaxA, la);
            tmaxB = fmaxf(tmaxB, lb);
        }

        {
            float nA = fmaxf(rmaxA, tmaxA);
            float fA = exp2f(rmaxA - nA);
            rmaxA = nA; ssumA *= fA;
            u64 fA2 = pack2(fA, fA);
            float nB = fmaxf(rmaxB, tmaxB);
            float fB = exp2f(rmaxB - nB);
            rmaxB = nB; ssumB *= fB;
            u64 fB2 = pack2(fB, fB);
            #pragma unroll
            for (int i = 0; i < 16; i++) {
                accA[i] = mul2(accA[i], fA2);
                accB[i] = mul2(accB[i], fB2);
            }
        }

        #pragma unroll 2
        for (int j = 0; j < 32; j++) {
            float ea = exp2f(bs[t*33 + j]       - rmaxA);
            float eb = exp2f(bs[(t+128)*33 + j] - rmaxB);
            ssumA += ea;
            ssumB += eb;
            u64 ea2 = pack2(ea, ea);
            u64 eb2 = pack2(eb, eb);
            const ulonglong2* v2 = (const ulonglong2*)(vs + j*32);
            #pragma unroll
            for (int i = 0; i < 8; i++) {
                ulonglong2 vv = v2[i];
                accA[2*i]   = fma2(ea2, vv.x, accA[2*i]);
                accA[2*i+1] = fma2(ea2, vv.y, accA[2*i+1]);
                accB[2*i]   = fma2(eb2, vv.x, accB[2*i]);
                accB[2*i+1] = fma2(eb2, vv.y, accB[2*i+1]);
            }
        }
    }

    {
        int pidx = (s*L + qa)*NH + h;
        g_pmax[pidx] = rmaxA;
        g_psum[pidx] = ssumA;
        u64* pa = (u64*)(g_pacc + (size_t)pidx*HD);
        #pragma unroll
        for (int i = 0; i < 16; i++) pa[i] = accA[i];
    }
    {
        int pidx = (s*L + qb)*NH + h;
        g_pmax[pidx] = rmaxB;
        g_psum[pidx] = ssumB;
        u64* pb = (u64*)(g_pacc + (size_t)pidx*HD);
        #pragma unroll
        for (int i = 0; i < 16; i++) pb[i] = accB[i];
    }
}

// ---------------- fused: comb + Wo + residual + LN + FF1 + FF2 + residual ----------------
__global__ void __launch_bounds__(256)
k_mlp(const float* __restrict__ Wo, const float* __restrict__ Wt1,
      const float* __restrict__ Wt2)
{
    constexpr int R = 8;
    __shared__ u64  xs2 [R*128];
    __shared__ u64  ff2 [R*512];
    __shared__ float qrow[R*128];

    int r0 = blockIdx.x * R;
    int t  = threadIdx.x;

    for (int idx = t; idx < R*128; idx += 256) {
        int row = idx >> 7, c = idx & 127;
        int h = c >> 5, d = c & 31;
        int q = r0 + row;
        float gm = -1e30f;
        #pragma unroll 4
        for (int s = 0; s < KSPLIT; s++)
            gm = fmaxf(gm, g_pmax[(s*L + q)*NH + h]);
        float denom = 0.f, o = 0.f;
        #pragma unroll 4
        for (int s = 0; s < KSPLIT; s++) {
            int pidx = (s*L + q)*NH + h;
            float f = exp2f(g_pmax[pidx] - gm);
            denom += g_psum[pidx] * f;
            o     += g_pacc[(size_t)pidx*HD + d] * f;
        }
        o /= denom;
        xs2[idx] = pack2(o, o);
    }
    __syncthreads();

    {
        int cp = t & 63, g = t >> 6;
        const u64* Wo2 = (const u64*)Wo + cp;
        u64 acc[2] = {0ull, 0ull};
        #pragma unroll 4
        for (int k = 0; k < 128; k++) {
            u64 w2 = Wo2[(size_t)k*64];
            acc[0] = fma2(xs2[(g*2+0)*128 + k], w2, acc[0]);
            acc[1] = fma2(xs2[(g*2+1)*128 + k], w2, acc[1]);
        }
        #pragma unroll
        for (int r = 0; r < 2; r++) {
            int row = g*2 + r;
            int q = r0 + row;
            float lo, hi; unpack2(acc[r], lo, hi);
            lo += g_Q[(size_t)q*128 + 2*cp];
            hi += g_Q[(size_t)q*128 + 2*cp + 1];
            qrow[row*128 + 2*cp]     = lo;
            qrow[row*128 + 2*cp + 1] = hi;
        }
    }
    __syncthreads();

    {
        int w = t >> 5, lane = t & 31;
        float4 v = ((const float4*)(qrow + w*128))[lane];
        float s  = v.x + v.y + v.z + v.w;
        float ss = v.x*v.x + v.y*v.y + v.z*v.z + v.w*v.w;
        #pragma unroll
        for (int o = 16; o >= 1; o >>= 1) {
            s  += __shfl_xor_sync(0xffffffffu, s,  o);
            ss += __shfl_xor_sync(0xffffffffu, ss, o);
        }
        float mu   = s * (1.f/128.f);
        float rstd = rsqrtf(ss * (1.f/128.f) - mu*mu + 1e-5f);
        u64* xd = xs2 + w*128 + lane*4;
        float n0 = (v.x - mu)*rstd, n1 = (v.y - mu)*rstd;
        float n2 = (v.z - mu)*rstd, n3 = (v.w - mu)*rstd;
        xd[0] = pack2(n0, n0); xd[1] = pack2(n1, n1);
        xd[2] = pack2(n2, n2); xd[3] = pack2(n3, n3);
    }
    __syncthreads();

    {
        int cp1 = t;
        const u64* W12 = (const u64*)Wt1 + cp1;
        u64 a1[8];
        #pragma unroll
        for (int r = 0; r < 8; r++) a1[r] = 0ull;
        #pragma unroll 4
        for (int k = 0; k < 128; k++) {
            u64 w2 = W12[(size_t)k*256];
            #pragma unroll
            for (int r = 0; r < 8; r++)
                a1[r] = fma2(xs2[r*128 + k], w2, a1[r]);
        }
        #pragma unroll
        for (int r = 0; r < 8; r++) {
            float lo, hi; unpack2(a1[r], lo, hi);
            lo = fmaxf(lo, 0.f); hi = fmaxf(hi, 0.f);
            ff2[r*512 + 2*cp1]     = pack2(lo, lo);
            ff2[r*512 + 2*cp1 + 1] = pack2(hi, hi);
        }
    }
    __syncthreads();

    {
        int cp = t & 63, g = t >> 6;
        const u64* W22 = (const u64*)Wt2 + cp;
        u64 acc[2] = {0ull, 0ull};
        #pragma unroll 4
        for (int k = 0; k < 512; k++) {
            u64 w2 = W22[(size_t)k*64];
            acc[0] = fma2(ff2[(g*2+0)*512 + k], w2, acc[0]);
            acc[1] = fma2(ff2[(g*2+1)*512 + k], w2, acc[1]);
        }
        #pragma unroll
        for (int r = 0; r < 2; r++) {
            int row = g*2 + r;
            int q = r0 + row;
            float lo, hi; unpack2(acc[r], lo, hi);
            lo += qrow[row*128 + 2*cp];
            hi += qrow[row*128 + 2*cp + 1];
            g_Q[(size_t)q*128 + 2*cp]     = lo;
            g_Q[(size_t)q*128 + 2*cp + 1] = hi;
        }
    }
}

// ---------------- final: copy Q to out + relu(Q @ Wq_tok) ----------------
__global__ void __launch_bounds__(256)
k_out(const float* __restrict__ X, const float* __restrict__ W,
      float* __restrict__ OUT, float* __restrict__ outQ)
{
    constexpr int R = 16;
    constexpr int NSUB = 128;
    __shared__ u64 xs2[R*128];
    int r0 = blockIdx.x * R;
    int t  = threadIdx.x;
    int colOff = blockIdx.y * NSUB;

    {
        const float* xb = X + (size_t)r0*128;
        float* qb = outQ + (size_t)r0*128;
        bool docopy = (blockIdx.y == 0);
        for (int i = t; i < R*128; i += 256) {
            float v = xb[i];
            xs2[i] = pack2(v, v);
            if (docopy) qb[i] = v;
        }
    }
    __syncthreads();

    int cp = t & 63, g = t >> 6;
    const u64* Wp = (const u64*)W + (colOff >> 1) + cp;
    u64 acc[4] = {0ull, 0ull, 0ull, 0ull};
    #pragma unroll 4
    for (int k = 0; k < 128; k++) {
        u64 w2 = Wp[(size_t)k*(CT/2)];
        #pragma unroll
        for (int r = 0; r < 4; r++)
            acc[r] = fma2(xs2[(g*4 + r)*128 + k], w2, acc[r]);
    }
    #pragma unroll
    for (int r = 0; r < 4; r++) {
        float lo, hi; unpack2(acc[r], lo, hi);
        lo = fmaxf(lo, 0.f); hi = fmaxf(hi, 0.f);
        float* o = OUT + (size_t)(r0 + g*4 + r)*CT + colOff + 2*cp;
        o[0] = lo; o[1] = hi;
    }
}

// ---------------- segment mean ----------------
__global__ void k_seg(const float* __restrict__ pQ, const int* __restrict__ tok,
                      float* __restrict__ outA)
{
    __shared__ int slo, shi;
    int i = blockIdx.x;
    if (threadIdx.x == 0) {
        int lo = 0, hi = L;
        while (lo < hi) { int mid = (lo+hi) >> 1; if (tok[mid] < i) lo = mid+1; else hi = mid; }
        slo = lo;
        int lo2 = lo, hi2 = L;
        while (lo2 < hi2) { int mid = (lo2+hi2) >> 1; if (tok[mid] < i+1) lo2 = mid+1; else hi2 = mid; }
        shi = lo2;
    }
    __syncthreads();
    int lo = slo, hi = shi;
    float inv = (hi > lo) ? 1.f/(float)(hi - lo) : 0.f;
    int c = threadIdx.x;
    float a = 0.f;
    for (int at = lo; at < hi; at++) a += pQ[(size_t)at*CT + c];
    outA[(size_t)i*CT + c] = a * inv;
}

// ---------------- launch ----------------
extern "C" void kernel_launch(void* const* d_in, const int* in_sizes, int n_in,
                              void* d_out, int out_size)
{
    const float* pos    = (const float*)d_in[0];
    const float* charge = (const float*)d_in[1];
    const float* elem   = (const float*)d_in[2];
    const float* chars  = (const float*)d_in[3];
    const int*   uid    = (const int*)  d_in[4];
    const int*   tok    = (const int*)  d_in[5];
    const float* Win    = (const float*)d_in[6];
    const float* Wd     = (const float*)d_in[7];
    const float* Wiv    = (const float*)d_in[8];
    const float* Wvmw   = (const float*)d_in[9];
    const float* Wsl    = (const float*)d_in[10];
    const float* Wsm    = (const float*)d_in[11];
    const float* Wp1    = (const float*)d_in[12];
    const float* Wp2    = (const float*)d_in[13];
    const float* Wp3    = (const float*)d_in[14];
    const float* Wqtok  = (const float*)d_in[15];
    const float* Wq     = (const float*)d_in[16];
    const float* Wk     = (const float*)d_in[17];
    const float* Wv     = (const float*)d_in[18];
    const float* Wb     = (const float*)d_in[19];
    const float* Wo     = (const float*)d_in[20];
    const float* Wt1    = (const float*)d_in[21];
    const float* Wt2    = (const float*)d_in[22];

    float* out   = (float*)d_out;
    float* outA  = out + OFF_A;
    float* outQ  = out + OFF_Q;
    float* outCL = out + OFF_CL;
    float* outP  = out + OFF_P;

    float *pQbuf, *pFF;
    cudaGetSymbolAddress((void**)&pQbuf, g_Q);
    cudaGetSymbolAddress((void**)&pFF,   g_ff);

    k_cl  <<<L, 128>>>(pos, charge, elem, chars, Win, Wsl, Wsm, outCL);
    k_pair<<<dim3(4, L), 128>>>(pos, uid, Wd, Wiv, Wvmw, Wp1, Wp2, Wp3, Wb, outP);

    for (int b = 0; b < NBLK; b++) {
        k_qkv<<<dim3(L/16, 3), 256>>>(pQbuf, Wq + (size_t)b*CA*CA,
                                      Wk + (size_t)b*CA*CA, Wv + (size_t)b*CA*CA);
        k_attn_split<<<dim3(L/256, NH, KSPLIT), 128>>>(b);
        k_mlp<<<L/8, 256>>>(Wo + (size_t)b*CA*CA, Wt1 + (size_t)b*CA*FFDIM,
                            Wt2 + (size_t)b*FFDIM*CA);
    }

    k_out<<<dim3(L/16, 3), 256>>>(pQbuf, Wqtok, pFF, outQ);
    k_seg<<<TOKS, CT>>>(pFF, tok, outA);
}

// round 15
// speedup vs baseline: 1.0937x; 1.0937x over previous
#include <cuda_runtime.h>
#include <math.h>

#define L 2048
#define TOKS 512
#define CA 128
#define CP 16
#define CT 384
#define NH 4
#define HD 32
#define FFDIM 512
#define NBLK 3
#define F1D 388
#define KSPLIT 32

#define OFF_A 0
#define OFF_Q (TOKS*CT)
#define OFF_CL (OFF_Q + L*CA)
#define OFF_P (OFF_CL + L*CA)

typedef unsigned long long u64;

// ---------------- f32x2 helpers ----------------
__device__ __forceinline__ u64 pack2(float lo, float hi) {
    u64 r; asm("mov.b64 %0, {%1, %2};" : "=l"(r) : "f"(lo), "f"(hi)); return r;
}
__device__ __forceinline__ void unpack2(u64 v, float& lo, float& hi) {
    asm("mov.b64 {%0, %1}, %2;" : "=f"(lo), "=f"(hi) : "l"(v));
}
__device__ __forceinline__ u64 fma2(u64 a, u64 b, u64 c) {
    u64 d; asm("fma.rn.f32x2 %0, %1, %2, %3;" : "=l"(d) : "l"(a), "l"(b), "l"(c)); return d;
}
__device__ __forceinline__ u64 mul2(u64 a, u64 b) {
    u64 d; asm("mul.rn.f32x2 %0, %1, %2;" : "=l"(d) : "l"(a), "l"(b)); return d;
}
__device__ __forceinline__ u64 add2(u64 a, u64 b) {
    u64 d; asm("add.rn.f32x2 %0, %1, %2;" : "=l"(d) : "l"(a), "l"(b)); return d;
}
__device__ __forceinline__ u64 relu2(u64 v) {
    float lo, hi; unpack2(v, lo, hi);
    return pack2(fmaxf(lo, 0.f), fmaxf(hi, 0.f));
}
__device__ __forceinline__ void splat2(u64 v, u64& s0, u64& s1) {
    float lo, hi; unpack2(v, lo, hi);
    s0 = pack2(lo, lo); s1 = pack2(hi, hi);
}

// ---------------- scratch ----------------
__device__ float g_Q  [L*CA];
__device__ float g_qm [L*CA];
__device__ float g_km [L*CA];
__device__ float g_vm [L*CA];
__device__ float g_ff [L*FFDIM];
__device__ float g_sl [L*CP];
__device__ float g_sm [L*CP];
__device__ float g_bias[(size_t)NBLK*NH*L*L];           // [b][h][l][m]
__device__ float g_pmax[KSPLIT*L*NH];
__device__ float g_psum[KSPLIT*L*NH];
__device__ float g_pacc[(size_t)KSPLIT*L*NH*HD];

// ---------------- C_L = concat(feat)@W_in ; seeds Q ; fused sl/sm projections ----------------
__global__ void k_cl(const float* __restrict__ pos, const float* __restrict__ charge,
                     const float* __restrict__ elem, const float* __restrict__ chars,
                     const float* __restrict__ Win, const float* __restrict__ Wsl,
                     const float* __restrict__ Wsm, float* __restrict__ outCL)
{
    __shared__ float f[F1D];
    __shared__ float r[128];
    int l = blockIdx.x, t = threadIdx.x;
    if (t < 3)  f[t]   = pos[l*3 + t];
    if (t == 3) f[3]   = charge[l];
    f[4   + t] = elem [l*128 + t];
    f[132 + t] = chars[l*256 + t];
    f[260 + t] = chars[l*256 + 128 + t];
    __syncthreads();
    float acc = 0.f;
    #pragma unroll 4
    for (int k = 0; k < F1D; k++) acc += f[k] * Win[(size_t)k*CA + t];
    outCL[(size_t)l*CA + t] = acc;
    g_Q  [(size_t)l*CA + t] = acc;
    r[t] = fmaxf(acc, 0.f);
    __syncthreads();
    if (t < 16) {
        float a = 0.f;
        #pragma unroll 4
        for (int k = 0; k < 128; k++) a += r[k] * Wsl[k*16 + t];
        g_sl[l*16 + t] = a;
    } else if (t < 32) {
        int c = t - 16;
        float a = 0.f;
        #pragma unroll 4
        for (int k = 0; k < 128; k++) a += r[k] * Wsm[k*16 + c];
        g_sm[l*16 + c] = a;
    }
}

// ---------------- pair features + MLP + fused bias — channel-packed f32x2, 1 atom/thread ----------------
__global__ void __launch_bounds__(256)
k_pair(const float* __restrict__ pos, const int* __restrict__ uid,
       const float* __restrict__ Wd,  const float* __restrict__ Wiv,
       const float* __restrict__ Wvm, const float* __restrict__ Wp1,
       const float* __restrict__ Wp2, const float* __restrict__ Wp3,
       const float* __restrict__ Wb,  float* __restrict__ outP)
{
    __shared__ u64 wd2[24], wiv2[8], wvm2[8], w1[128], w2[128], w3[128], wb2[96], sl2[8];
    __shared__ float pl[3];
    __shared__ int ul;
    int l = blockIdx.y;
    int t = threadIdx.x;
    int m = blockIdx.x*256 + t;

    if (t < 128) {
        w1[t] = ((const u64*)Wp1)[t];
        w3[t] = ((const u64*)Wp3)[t];
    } else {
        int u = t - 128;
        w2[u] = ((const u64*)Wp2)[u];
    }
    if (t < 24)                wd2[t]     = ((const u64*)Wd)[t];
    else if (t < 32)           wiv2[t-24] = ((const u64*)Wiv)[t-24];
    else if (t < 40)           wvm2[t-32] = ((const u64*)Wvm)[t-32];
    else if (t >= 40 && t < 136) wb2[t-40] = ((const u64*)Wb)[t-40];
    if (t >= 136 && t < 144)   sl2[t-136] = ((const u64*)(g_sl + l*16))[t-136];
    if (t >= 144 && t < 147)   pl[t-144]  = pos[l*3 + (t-144)];
    if (t == 147)              ul = uid[l];

    float mx = pos[m*3+0], my = pos[m*3+1], mz = pos[m*3+2];
    int   um = uid[m];
    __syncthreads();

    float d0 = pl[0] - mx, d1 = pl[1] - my, d2 = pl[2] - mz;
    float iv = 1.f / (1.f + sqrtf(d0*d0 + d1*d1 + d2*d2));
    float vf = (ul == um) ? 1.f : 0.f;
    u64 d0s = pack2(d0, d0), d1s = pack2(d1, d1), d2s = pack2(d2, d2);
    u64 ivs = pack2(iv, iv), vfs = pack2(vf, vf);

    u64 p[8];
    {
        const ulonglong2* smp = (const ulonglong2*)(g_sm + (size_t)m*16);
        #pragma unroll
        for (int i = 0; i < 4; i++) {
            ulonglong2 sm2v = smp[i];
            u64 t0 = wvm2[2*i];
            t0 = fma2(ivs, wiv2[2*i],    t0);
            t0 = fma2(d2s, wd2[16+2*i],  t0);
            t0 = fma2(d1s, wd2[8+2*i],   t0);
            t0 = fma2(d0s, wd2[2*i],     t0);
            p[2*i]   = fma2(vfs, t0, add2(sl2[2*i], sm2v.x));
            u64 t1 = wvm2[2*i+1];
            t1 = fma2(ivs, wiv2[2*i+1],   t1);
            t1 = fma2(d2s, wd2[16+2*i+1], t1);
            t1 = fma2(d1s, wd2[8+2*i+1],  t1);
            t1 = fma2(d0s, wd2[2*i+1],    t1);
            p[2*i+1] = fma2(vfs, t1, add2(sl2[2*i+1], sm2v.y));
        }
    }

    u64 sp[16], a[8];

    #pragma unroll
    for (int j = 0; j < 8; j++) splat2(relu2(p[j]), sp[2*j], sp[2*j+1]);
    #pragma unroll
    for (int i = 0; i < 8; i++) {
        u64 acc = 0ull;
        #pragma unroll
        for (int j = 0; j < 16; j++) acc = fma2(sp[j], w1[j*8 + i], acc);
        a[i] = acc;
    }
    #pragma unroll
    for (int j = 0; j < 8; j++) splat2(relu2(a[j]), sp[2*j], sp[2*j+1]);
    #pragma unroll
    for (int i = 0; i < 8; i++) {
        u64 acc = 0ull;
        #pragma unroll
        for (int j = 0; j < 16; j++) acc = fma2(sp[j], w2[j*8 + i], acc);
        a[i] = acc;
    }
    #pragma unroll
    for (int j = 0; j < 8; j++) splat2(relu2(a[j]), sp[2*j], sp[2*j+1]);
    #pragma unroll
    for (int i = 0; i < 8; i++) {
        u64 acc = 0ull;
        #pragma unroll
        for (int j = 0; j < 16; j++) acc = fma2(sp[j], w3[j*8 + i], acc);
        p[i] = add2(p[i], acc);
    }

    {
        ulonglong2* dst = (ulonglong2*)(outP + ((size_t)l*L + m)*16);
        #pragma unroll
        for (int i = 0; i < 4; i++) {
            ulonglong2 v; v.x = p[2*i]; v.y = p[2*i+1];
            dst[i] = v;
        }
    }

    #pragma unroll
    for (int j = 0; j < 8; j++) splat2(p[j], sp[2*j], sp[2*j+1]);
    #pragma unroll
    for (int b = 0; b < NBLK; b++) {
        #pragma unroll
        for (int hp = 0; hp < 2; hp++) {
            u64 acc = 0ull;
            #pragma unroll
            for (int c = 0; c < 16; c++) acc = fma2(sp[c], wb2[b*32 + c*2 + hp], acc);
            float blo, bhi; unpack2(acc, blo, bhi);
            float* base = g_bias + ((size_t)(b*NH + 2*hp)*L + l)*L + m;
            base[0]           = blo;
            base[(size_t)L*L] = bhi;
        }
    }
}

// ---------------- fused QKV (LN + 3 gemms), R=16 rows/CTA ----------------
__global__ void __launch_bounds__(256)
k_qkv(const float* __restrict__ X, const float* __restrict__ Wq,
      const float* __restrict__ Wk, const float* __restrict__ Wv)
{
    const float* W = (blockIdx.y == 0) ? Wq : (blockIdx.y == 1) ? Wk : Wv;
    float* O = (blockIdx.y == 0) ? g_qm : (blockIdx.y == 1) ? g_km : g_vm;

    constexpr int R = 16;
    __shared__ u64 xs2[R*128];
    int r0 = blockIdx.x * R;
    int t  = threadIdx.x;

    {
        int r  = t >> 4, c0 = t & 15;
        const float* xr = X + (size_t)(r0 + r)*128;
        float v[8]; float s = 0.f, ss = 0.f;
        #pragma unroll
        for (int i = 0; i < 8; i++) { v[i] = xr[c0 + i*16]; s += v[i]; ss += v[i]*v[i]; }
        #pragma unroll
        for (int o = 8; o >= 1; o >>= 1) {
            s  += __shfl_xor_sync(0xffffffffu, s,  o);
            ss += __shfl_xor_sync(0xffffffffu, ss, o);
        }
        float mu   = s * (1.f/128.f);
        float rstd = rsqrtf(ss * (1.f/128.f) - mu*mu + 1e-5f);
        #pragma unroll
        for (int i = 0; i < 8; i++) {
            float nv = (v[i] - mu) * rstd;
            xs2[r*128 + c0 + i*16] = pack2(nv, nv);
        }
    }
    __syncthreads();

    int cp = t & 63;
    int g  = t >> 6;
    const u64* Wp = (const u64*)W + cp;
    u64 acc[4] = {0ull, 0ull, 0ull, 0ull};
    #pragma unroll 4
    for (int k = 0; k < 128; k++) {
        u64 w2 = Wp[(size_t)k*64];
        #pragma unroll
        for (int r = 0; r < 4; r++)
            acc[r] = fma2(xs2[(g*4 + r)*128 + k], w2, acc[r]);
    }
    #pragma unroll
    for (int r = 0; r < 4; r++) {
        float lo, hi; unpack2(acc[r], lo, hi);
        float* o = O + (size_t)(r0 + g*4 + r)*128 + 2*cp;
        o[0] = lo; o[1] = hi;
    }
}

// ---------------- attention v3b: 2 queries/thread, reg cap 170 for 3 CTAs/SM ----------------
__global__ void __launch_bounds__(128, 3) k_attn_split(int b)
{
    const float L2E = 1.4426950408889634f;
    const float SCALE_L2E = 0.1767766952966369f * L2E;

    int h  = blockIdx.y;
    int s  = blockIdx.z;
    int q0 = blockIdx.x * 256;
    int t  = threadIdx.x;
    int qa = q0 + t;
    int qb = qa + 128;

    __shared__ alignas(16) float ks[32*32];
    __shared__ alignas(16) float vs[32*32];
    __shared__ float bs[256*33];

    u64 qA[16], qB[16];
    {
        u64 sc2 = pack2(SCALE_L2E, SCALE_L2E);
        const ulonglong2* pa = (const ulonglong2*)(g_qm + (size_t)qa*CA + h*HD);
        const ulonglong2* pb = (const ulonglong2*)(g_qm + (size_t)qb*CA + h*HD);
        #pragma unroll
        for (int i = 0; i < 8; i++) {
            ulonglong2 va = pa[i], vb = pb[i];
            qA[2*i] = mul2(va.x, sc2); qA[2*i+1] = mul2(va.y, sc2);
            qB[2*i] = mul2(vb.x, sc2); qB[2*i+1] = mul2(vb.y, sc2);
        }
    }

    float rmaxA = -1e30f, rmaxB = -1e30f, ssumA = 0.f, ssumB = 0.f;
    u64 accA[16], accB[16];
    #pragma unroll
    for (int i = 0; i < 16; i++) { accA[i] = 0ull; accB[i] = 0ull; }

    const float* bsrc_base = g_bias + ((size_t)(b*NH + h)*L + q0)*L;
    int m_begin = s * (L/KSPLIT);
    int m_end   = m_begin + (L/KSPLIT);

    for (int m0 = m_begin; m0 < m_end; m0 += 32) {
        __syncthreads();
        for (int i = t; i < 256; i += 128) {
            int j = i >> 3, dq = i & 7;
            ((float4*)ks)[i] = ((const float4*)g_km)[(size_t)(m0+j)*32 + h*8 + dq];
            ((float4*)vs)[i] = ((const float4*)g_vm)[(size_t)(m0+j)*32 + h*8 + dq];
        }
        for (int i = t; i < 2048; i += 128) {
            int t2 = i >> 3, jv = i & 7;
            float4 v = *(const float4*)(bsrc_base + (size_t)t2*L + m0 + jv*4);
            float* d = bs + t2*33 + jv*4;
            d[0] = v.x*L2E; d[1] = v.y*L2E; d[2] = v.z*L2E; d[3] = v.w*L2E;
        }
        __syncthreads();

        float tmaxA = -1e30f, tmaxB = -1e30f;
        #pragma unroll 2
        for (int j = 0; j < 32; j++) {
            const ulonglong2* k2 = (const ulonglong2*)(ks + j*32);
            u64 dA0 = pack2(bs[t*33 + j], 0.f);
            u64 dA1 = 0ull;
            u64 dB0 = pack2(bs[(t+128)*33 + j], 0.f);
            u64 dB1 = 0ull;
            #pragma unroll
            for (int i = 0; i < 8; i++) {
                ulonglong2 kk = k2[i];
                dA0 = fma2(qA[2*i],   kk.x, dA0);
                dA1 = fma2(qA[2*i+1], kk.y, dA1);
                dB0 = fma2(qB[2*i],   kk.x, dB0);
                dB1 = fma2(qB[2*i+1], kk.y, dB1);
            }
            u64 dA = add2(dA0, dA1);
            u64 dB = add2(dB0, dB1);
            float a_lo, a_hi, b_lo, b_hi;
            unpack2(dA, a_lo, a_hi);
            unpack2(dB, b_lo, b_hi);
            float la = a_lo + a_hi, lb = b_lo + b_hi;
            bs[t*33 + j]       = la;
            bs[(t+128)*33 + j] = lb;
            tmaxA = fmaxf(tmaxA, la);
            tmaxB = fmaxf(tmaxB, lb);
        }

        {
            float nA = fmaxf(rmaxA, tmaxA);
            float fA = exp2f(rmaxA - nA);
            rmaxA = nA; ssumA *= fA;
            u64 fA2 = pack2(fA, fA);
            float nB = fmaxf(rmaxB, tmaxB);
            float fB = exp2f(rmaxB - nB);
            rmaxB = nB; ssumB *= fB;
            u64 fB2 = pack2(fB, fB);
            #pragma unroll
            for (int i = 0; i < 16; i++) {
                accA[i] = mul2(accA[i], fA2);
                accB[i] = mul2(accB[i], fB2);
            }
        }

        #pragma unroll 2
        for (int j = 0; j < 32; j++) {
            float ea = exp2f(bs[t*33 + j]       - rmaxA);
            float eb = exp2f(bs[(t+128)*33 + j] - rmaxB);
            ssumA += ea;
            ssumB += eb;
            u64 ea2 = pack2(ea, ea);
            u64 eb2 = pack2(eb, eb);
            const ulonglong2* v2 = (const ulonglong2*)(vs + j*32);
            #pragma unroll
            for (int i = 0; i < 8; i++) {
                ulonglong2 vv = v2[i];
                accA[2*i]   = fma2(ea2, vv.x, accA[2*i]);
                accA[2*i+1] = fma2(ea2, vv.y, accA[2*i+1]);
                accB[2*i]   = fma2(eb2, vv.x, accB[2*i]);
                accB[2*i+1] = fma2(eb2, vv.y, accB[2*i+1]);
            }
        }
    }

    {
        int pidx = (s*L + qa)*NH + h;
        g_pmax[pidx] = rmaxA;
        g_psum[pidx] = ssumA;
        u64* pa = (u64*)(g_pacc + (size_t)pidx*HD);
        #pragma unroll
        for (int i = 0; i < 16; i++) pa[i] = accA[i];
    }
    {
        int pidx = (s*L + qb)*NH + h;
        g_pmax[pidx] = rmaxB;
        g_psum[pidx] = ssumB;
        u64* pb = (u64*)(g_pacc + (size_t)pidx*HD);
        #pragma unroll
        for (int i = 0; i < 16; i++) pb[i] = accB[i];
    }
}

// ---------------- fused: comb + Wo + residual + LN + FF1 + FF2 + residual ----------------
__global__ void __launch_bounds__(256)
k_mlp(const float* __restrict__ Wo, const float* __restrict__ Wt1,
      const float* __restrict__ Wt2)
{
    constexpr int R = 8;
    __shared__ u64  xs2 [R*128];
    __shared__ u64  ff2 [R*512];
    __shared__ float qrow[R*128];

    int r0 = blockIdx.x * R;
    int t  = threadIdx.x;

    for (int idx = t; idx < R*128; idx += 256) {
        int row = idx >> 7, c = idx & 127;
        int h = c >> 5, d = c & 31;
        int q = r0 + row;
        float gm = -1e30f;
        #pragma unroll 4
        for (int s = 0; s < KSPLIT; s++)
            gm = fmaxf(gm, g_pmax[(s*L + q)*NH + h]);
        float denom = 0.f, o = 0.f;
        #pragma unroll 4
        for (int s = 0; s < KSPLIT; s++) {
            int pidx = (s*L + q)*NH + h;
            float f = exp2f(g_pmax[pidx] - gm);
            denom += g_psum[pidx] * f;
            o     += g_pacc[(size_t)pidx*HD + d] * f;
        }
        o /= denom;
        xs2[idx] = pack2(o, o);
    }
    __syncthreads();

    {
        int cp = t & 63, g = t >> 6;
        const u64* Wo2 = (const u64*)Wo + cp;
        u64 acc[2] = {0ull, 0ull};
        #pragma unroll 4
        for (int k = 0; k < 128; k++) {
            u64 w2 = Wo2[(size_t)k*64];
            acc[0] = fma2(xs2[(g*2+0)*128 + k], w2, acc[0]);
            acc[1] = fma2(xs2[(g*2+1)*128 + k], w2, acc[1]);
        }
        #pragma unroll
        for (int r = 0; r < 2; r++) {
            int row = g*2 + r;
            int q = r0 + row;
            float lo, hi; unpack2(acc[r], lo, hi);
            lo += g_Q[(size_t)q*128 + 2*cp];
            hi += g_Q[(size_t)q*128 + 2*cp + 1];
            qrow[row*128 + 2*cp]     = lo;
            qrow[row*128 + 2*cp + 1] = hi;
        }
    }
    __syncthreads();

    {
        int w = t >> 5, lane = t & 31;
        float4 v = ((const float4*)(qrow + w*128))[lane];
        float s  = v.x + v.y + v.z + v.w;
        float ss = v.x*v.x + v.y*v.y + v.z*v.z + v.w*v.w;
        #pragma unroll
        for (int o = 16; o >= 1; o >>= 1) {
            s  += __shfl_xor_sync(0xffffffffu, s,  o);
            ss += __shfl_xor_sync(0xffffffffu, ss, o);
        }
        float mu   = s * (1.f/128.f);
        float rstd = rsqrtf(ss * (1.f/128.f) - mu*mu + 1e-5f);
        u64* xd = xs2 + w*128 + lane*4;
        float n0 = (v.x - mu)*rstd, n1 = (v.y - mu)*rstd;
        float n2 = (v.z - mu)*rstd, n3 = (v.w - mu)*rstd;
        xd[0] = pack2(n0, n0); xd[1] = pack2(n1, n1);
        xd[2] = pack2(n2, n2); xd[3] = pack2(n3, n3);
    }
    __syncthreads();

    {
        int cp1 = t;
        const u64* W12 = (const u64*)Wt1 + cp1;
        u64 a1[8];
        #pragma unroll
        for (int r = 0; r < 8; r++) a1[r] = 0ull;
        #pragma unroll 4
        for (int k = 0; k < 128; k++) {
            u64 w2 = W12[(size_t)k*256];
            #pragma unroll
            for (int r = 0; r < 8; r++)
                a1[r] = fma2(xs2[r*128 + k], w2, a1[r]);
        }
        #pragma unroll
        for (int r = 0; r < 8; r++) {
            float lo, hi; unpack2(a1[r], lo, hi);
            lo = fmaxf(lo, 0.f); hi = fmaxf(hi, 0.f);
            ff2[r*512 + 2*cp1]     = pack2(lo, lo);
            ff2[r*512 + 2*cp1 + 1] = pack2(hi, hi);
        }
    }
    __syncthreads();

    {
        int cp = t & 63, g = t >> 6;
        const u64* W22 = (const u64*)Wt2 + cp;
        u64 acc[2] = {0ull, 0ull};
        #pragma unroll 4
        for (int k = 0; k < 512; k++) {
            u64 w2 = W22[(size_t)k*64];
            acc[0] = fma2(ff2[(g*2+0)*512 + k], w2, acc[0]);
            acc[1] = fma2(ff2[(g*2+1)*512 + k], w2, acc[1]);
        }
        #pragma unroll
        for (int r = 0; r < 2; r++) {
            int row = g*2 + r;
            int q = r0 + row;
            float lo, hi; unpack2(acc[r], lo, hi);
            lo += qrow[row*128 + 2*cp];
            hi += qrow[row*128 + 2*cp + 1];
            g_Q[(size_t)q*128 + 2*cp]     = lo;
            g_Q[(size_t)q*128 + 2*cp + 1] = hi;
        }
    }
}

// ---------------- final: copy Q to out + relu(Q @ Wq_tok) ----------------
__global__ void __launch_bounds__(256)
k_out(const float* __restrict__ X, const float* __restrict__ W,
      float* __restrict__ OUT, float* __restrict__ outQ)
{
    constexpr int R = 16;
    constexpr int NSUB = 128;
    __shared__ u64 xs2[R*128];
    int r0 = blockIdx.x * R;
    int t  = threadIdx.x;
    int colOff = blockIdx.y * NSUB;

    {
        const float* xb = X + (size_t)r0*128;
        float* qb = outQ + (size_t)r0*128;
        bool docopy = (blockIdx.y == 0);
        for (int i = t; i < R*128; i += 256) {
            float v = xb[i];
            xs2[i] = pack2(v, v);
            if (docopy) qb[i] = v;
        }
    }
    __syncthreads();

    int cp = t & 63, g = t >> 6;
    const u64* Wp = (const u64*)W + (colOff >> 1) + cp;
    u64 acc[4] = {0ull, 0ull, 0ull, 0ull};
    #pragma unroll 4
    for (int k = 0; k < 128; k++) {
        u64 w2 = Wp[(size_t)k*(CT/2)];
        #pragma unroll
        for (int r = 0; r < 4; r++)
            acc[r] = fma2(xs2[(g*4 + r)*128 + k], w2, acc[r]);
    }
    #pragma unroll
    for (int r = 0; r < 4; r++) {
        float lo, hi; unpack2(acc[r], lo, hi);
        lo = fmaxf(lo, 0.f); hi = fmaxf(hi, 0.f);
        float* o = OUT + (size_t)(r0 + g*4 + r)*CT + colOff + 2*cp;
        o[0] = lo; o[1] = hi;
    }
}

// ---------------- segment mean ----------------
__global__ void k_seg(const float* __restrict__ pQ, const int* __restrict__ tok,
                      float* __restrict__ outA)
{
    __shared__ int slo, shi;
    int i = blockIdx.x;
    if (threadIdx.x == 0) {
        int lo = 0, hi = L;
        while (lo < hi) { int mid = (lo+hi) >> 1; if (tok[mid] < i) lo = mid+1; else hi = mid; }
        slo = lo;
        int lo2 = lo, hi2 = L;
        while (lo2 < hi2) { int mid = (lo2+hi2) >> 1; if (tok[mid] < i+1) lo2 = mid+1; else hi2 = mid; }
        shi = lo2;
    }
    __syncthreads();
    int lo = slo, hi = shi;
    float inv = (hi > lo) ? 1.f/(float)(hi - lo) : 0.f;
    int c = threadIdx.x;
    float a = 0.f;
    for (int at = lo; at < hi; at++) a += pQ[(size_t)at*CT + c];
    outA[(size_t)i*CT + c] = a * inv;
}

// ---------------- launch ----------------
extern "C" void kernel_launch(void* const* d_in, const int* in_sizes, int n_in,
                              void* d_out, int out_size)
{
    const float* pos    = (const float*)d_in[0];
    const float* charge = (const float*)d_in[1];
    const float* elem   = (const float*)d_in[2];
    const float* chars  = (const float*)d_in[3];
    const int*   uid    = (const int*)  d_in[4];
    const int*   tok    = (const int*)  d_in[5];
    const float* Win    = (const float*)d_in[6];
    const float* Wd     = (const float*)d_in[7];
    const float* Wiv    = (const float*)d_in[8];
    const float* Wvmw   = (const float*)d_in[9];
    const float* Wsl    = (const float*)d_in[10];
    const float* Wsm    = (const float*)d_in[11];
    const float* Wp1    = (const float*)d_in[12];
    const float* Wp2    = (const float*)d_in[13];
    const float* Wp3    = (const float*)d_in[14];
    const float* Wqtok  = (const float*)d_in[15];
    const float* Wq     = (const float*)d_in[16];
    const float* Wk     = (const float*)d_in[17];
    const float* Wv     = (const float*)d_in[18];
    const float* Wb     = (const float*)d_in[19];
    const float* Wo     = (const float*)d_in[20];
    const float* Wt1    = (const float*)d_in[21];
    const float* Wt2    = (const float*)d_in[22];

    float* out   = (float*)d_out;
    float* outA  = out + OFF_A;
    float* outQ  = out + OFF_Q;
    float* outCL = out + OFF_CL;
    float* outP  = out + OFF_P;

    float *pQbuf, *pFF;
    cudaGetSymbolAddress((void**)&pQbuf, g_Q);
    cudaGetSymbolAddress((void**)&pFF,   g_ff);

    k_cl  <<<L, 128>>>(pos, charge, elem, chars, Win, Wsl, Wsm, outCL);
    k_pair<<<dim3(8, L), 256>>>(pos, uid, Wd, Wiv, Wvmw, Wp1, Wp2, Wp3, Wb, outP);

    for (int b = 0; b < NBLK; b++) {
        k_qkv<<<dim3(L/16, 3), 256>>>(pQbuf, Wq + (size_t)b*CA*CA,
                                      Wk + (size_t)b*CA*CA, Wv + (size_t)b*CA*CA);
        k_attn_split<<<dim3(L/256, NH, KSPLIT), 128>>>(b);
        k_mlp<<<L/8, 256>>>(Wo + (size_t)b*CA*CA, Wt1 + (size_t)b*CA*FFDIM,
                            Wt2 + (size_t)b*FFDIM*CA);
    }

    k_out<<<dim3(L/16, 3), 256>>>(pQbuf, Wqtok, pFF, outQ);
    k_seg<<<TOKS, CT>>>(pFF, tok, outA);
}

// round 16
// speedup vs baseline: 1.1091x; 1.0140x over previous
#include <cuda_runtime.h>
#include <math.h>

#define L 2048
#define TOKS 512
#define CA 128
#define CP 16
#define CT 384
#define NH 4
#define HD 32
#define FFDIM 512
#define NBLK 3
#define F1D 388
#define KSPLIT 32

#define OFF_A 0
#define OFF_Q (TOKS*CT)
#define OFF_CL (OFF_Q + L*CA)
#define OFF_P (OFF_CL + L*CA)

typedef unsigned long long u64;

// ---------------- f32x2 helpers ----------------
__device__ __forceinline__ u64 pack2(float lo, float hi) {
    u64 r; asm("mov.b64 %0, {%1, %2};" : "=l"(r) : "f"(lo), "f"(hi)); return r;
}
__device__ __forceinline__ void unpack2(u64 v, float& lo, float& hi) {
    asm("mov.b64 {%0, %1}, %2;" : "=f"(lo), "=f"(hi) : "l"(v));
}
__device__ __forceinline__ u64 fma2(u64 a, u64 b, u64 c) {
    u64 d; asm("fma.rn.f32x2 %0, %1, %2, %3;" : "=l"(d) : "l"(a), "l"(b), "l"(c)); return d;
}
__device__ __forceinline__ u64 mul2(u64 a, u64 b) {
    u64 d; asm("mul.rn.f32x2 %0, %1, %2;" : "=l"(d) : "l"(a), "l"(b)); return d;
}
__device__ __forceinline__ u64 add2(u64 a, u64 b) {
    u64 d; asm("add.rn.f32x2 %0, %1, %2;" : "=l"(d) : "l"(a), "l"(b)); return d;
}
__device__ __forceinline__ u64 relu2(u64 v) {
    float lo, hi; unpack2(v, lo, hi);
    return pack2(fmaxf(lo, 0.f), fmaxf(hi, 0.f));
}

// ---------------- scratch ----------------
__device__ float g_Q  [L*CA];
__device__ float g_qm [L*CA];
__device__ float g_km [L*CA];
__device__ float g_vm [L*CA];
__device__ float g_ff [L*FFDIM];
__device__ float g_sl [L*CP];
__device__ float g_sm [L*CP];
__device__ float g_bias[(size_t)NBLK*NH*L*L];           // [b][h][l][m]
__device__ float g_pmax[KSPLIT*L*NH];
__device__ float g_psum[KSPLIT*L*NH];
__device__ float g_pacc[(size_t)KSPLIT*L*NH*HD];

// ---------------- C_L = concat(feat)@W_in ; seeds Q ; fused sl/sm projections ----------------
__global__ void k_cl(const float* __restrict__ pos, const float* __restrict__ charge,
                     const float* __restrict__ elem, const float* __restrict__ chars,
                     const float* __restrict__ Win, const float* __restrict__ Wsl,
                     const float* __restrict__ Wsm, float* __restrict__ outCL)
{
    __shared__ float f[F1D];
    __shared__ float r[128];
    int l = blockIdx.x, t = threadIdx.x;
    if (t < 3)  f[t]   = pos[l*3 + t];
    if (t == 3) f[3]   = charge[l];
    f[4   + t] = elem [l*128 + t];
    f[132 + t] = chars[l*256 + t];
    f[260 + t] = chars[l*256 + 128 + t];
    __syncthreads();
    float acc = 0.f;
    #pragma unroll 4
    for (int k = 0; k < F1D; k++) acc += f[k] * Win[(size_t)k*CA + t];
    outCL[(size_t)l*CA + t] = acc;
    g_Q  [(size_t)l*CA + t] = acc;
    r[t] = fmaxf(acc, 0.f);
    __syncthreads();
    if (t < 16) {
        float a = 0.f;
        #pragma unroll 4
        for (int k = 0; k < 128; k++) a += r[k] * Wsl[k*16 + t];
        g_sl[l*16 + t] = a;
    } else if (t < 32) {
        int c = t - 16;
        float a = 0.f;
        #pragma unroll 4
        for (int k = 0; k < 128; k++) a += r[k] * Wsm[k*16 + c];
        g_sm[l*16 + c] = a;
    }
}

// ---------------- pair: channel-packed f32x2, splat-on-the-fly (low regs, 3 CTAs/SM) ----------------
__global__ void __launch_bounds__(256, 3)
k_pair(const float* __restrict__ pos, const int* __restrict__ uid,
       const float* __restrict__ Wd,  const float* __restrict__ Wiv,
       const float* __restrict__ Wvm, const float* __restrict__ Wp1,
       const float* __restrict__ Wp2, const float* __restrict__ Wp3,
       const float* __restrict__ Wb,  float* __restrict__ outP)
{
    __shared__ u64 wd2[24], wiv2[8], wvm2[8], w1[128], w2[128], w3[128], wb2[96], sl2[8];
    __shared__ float pl[3];
    __shared__ int ul;
    int l = blockIdx.y;
    int t = threadIdx.x;
    int m = blockIdx.x*256 + t;

    if (t < 128) {
        w1[t] = ((const u64*)Wp1)[t];
        w3[t] = ((const u64*)Wp3)[t];
    } else {
        int u = t - 128;
        w2[u] = ((const u64*)Wp2)[u];
    }
    if (t < 24)                wd2[t]     = ((const u64*)Wd)[t];
    else if (t < 32)           wiv2[t-24] = ((const u64*)Wiv)[t-24];
    else if (t < 40)           wvm2[t-32] = ((const u64*)Wvm)[t-32];
    else if (t >= 40 && t < 136) wb2[t-40] = ((const u64*)Wb)[t-40];
    if (t >= 136 && t < 144)   sl2[t-136] = ((const u64*)(g_sl + l*16))[t-136];
    if (t >= 144 && t < 147)   pl[t-144]  = pos[l*3 + (t-144)];
    if (t == 147)              ul = uid[l];

    float mx = pos[m*3+0], my = pos[m*3+1], mz = pos[m*3+2];
    int   um = uid[m];
    __syncthreads();

    float d0 = pl[0] - mx, d1 = pl[1] - my, d2 = pl[2] - mz;
    float iv = 1.f / (1.f + sqrtf(d0*d0 + d1*d1 + d2*d2));
    float vf = (ul == um) ? 1.f : 0.f;
    u64 d0s = pack2(d0, d0), d1s = pack2(d1, d1), d2s = pack2(d2, d2);
    u64 ivs = pack2(iv, iv), vfs = pack2(vf, vf);

    u64 p[8];
    {
        const ulonglong2* smp = (const ulonglong2*)(g_sm + (size_t)m*16);
        #pragma unroll
        for (int i = 0; i < 4; i++) {
            ulonglong2 sm2v = smp[i];
            u64 t0 = wvm2[2*i];
            t0 = fma2(ivs, wiv2[2*i],    t0);
            t0 = fma2(d2s, wd2[16+2*i],  t0);
            t0 = fma2(d1s, wd2[8+2*i],   t0);
            t0 = fma2(d0s, wd2[2*i],     t0);
            p[2*i]   = fma2(vfs, t0, add2(sl2[2*i], sm2v.x));
            u64 t1 = wvm2[2*i+1];
            t1 = fma2(ivs, wiv2[2*i+1],   t1);
            t1 = fma2(d2s, wd2[16+2*i+1], t1);
            t1 = fma2(d1s, wd2[8+2*i+1],  t1);
            t1 = fma2(d0s, wd2[2*i+1],    t1);
            p[2*i+1] = fma2(vfs, t1, add2(sl2[2*i+1], sm2v.y));
        }
    }

    u64 r[8], a[8];

    // ---- layer 1: a = splat(relu(p)) @ W1, splat on-the-fly (j ascending) ----
    #pragma unroll
    for (int c = 0; c < 8; c++) r[c] = relu2(p[c]);
    #pragma unroll
    for (int i = 0; i < 8; i++) a[i] = 0ull;
    #pragma unroll
    for (int jj = 0; jj < 8; jj++) {
        float lo, hi; unpack2(r[jj], lo, hi);
        u64 s0 = pack2(lo, lo);
        #pragma unroll
        for (int i = 0; i < 8; i++) a[i] = fma2(s0, w1[(2*jj)*8 + i], a[i]);
        u64 s1 = pack2(hi, hi);
        #pragma unroll
        for (int i = 0; i < 8; i++) a[i] = fma2(s1, w1[(2*jj+1)*8 + i], a[i]);
    }
    // ---- layer 2 ----
    #pragma unroll
    for (int c = 0; c < 8; c++) r[c] = relu2(a[c]);
    #pragma unroll
    for (int i = 0; i < 8; i++) a[i] = 0ull;
    #pragma unroll
    for (int jj = 0; jj < 8; jj++) {
        float lo, hi; unpack2(r[jj], lo, hi);
        u64 s0 = pack2(lo, lo);
        #pragma unroll
        for (int i = 0; i < 8; i++) a[i] = fma2(s0, w2[(2*jj)*8 + i], a[i]);
        u64 s1 = pack2(hi, hi);
        #pragma unroll
        for (int i = 0; i < 8; i++) a[i] = fma2(s1, w2[(2*jj+1)*8 + i], a[i]);
    }
    // ---- layer 3 + residual ----
    #pragma unroll
    for (int c = 0; c < 8; c++) r[c] = relu2(a[c]);
    #pragma unroll
    for (int i = 0; i < 8; i++) a[i] = 0ull;
    #pragma unroll
    for (int jj = 0; jj < 8; jj++) {
        float lo, hi; unpack2(r[jj], lo, hi);
        u64 s0 = pack2(lo, lo);
        #pragma unroll
        for (int i = 0; i < 8; i++) a[i] = fma2(s0, w3[(2*jj)*8 + i], a[i]);
        u64 s1 = pack2(hi, hi);
        #pragma unroll
        for (int i = 0; i < 8; i++) a[i] = fma2(s1, w3[(2*jj+1)*8 + i], a[i]);
    }
    #pragma unroll
    for (int i = 0; i < 8; i++) p[i] = add2(p[i], a[i]);

    // store P row
    {
        ulonglong2* dst = (ulonglong2*)(outP + ((size_t)l*L + m)*16);
        #pragma unroll
        for (int i = 0; i < 4; i++) {
            ulonglong2 v; v.x = p[2*i]; v.y = p[2*i+1];
            dst[i] = v;
        }
    }

    // bias: 3 blocks x 2 head-pairs, splat on-the-fly (c ascending)
    u64 bacc[6];
    #pragma unroll
    for (int o = 0; o < 6; o++) bacc[o] = 0ull;
    #pragma unroll
    for (int jj = 0; jj < 8; jj++) {
        float lo, hi; unpack2(p[jj], lo, hi);
        u64 s0 = pack2(lo, lo);
        #pragma unroll
        for (int o = 0; o < 6; o++) {
            int b = o >> 1, hp = o & 1;
            bacc[o] = fma2(s0, wb2[b*32 + (2*jj)*2 + hp], bacc[o]);
        }
        u64 s1 = pack2(hi, hi);
        #pragma unroll
        for (int o = 0; o < 6; o++) {
            int b = o >> 1, hp = o & 1;
            bacc[o] = fma2(s1, wb2[b*32 + (2*jj+1)*2 + hp], bacc[o]);
        }
    }
    #pragma unroll
    for (int o = 0; o < 6; o++) {
        int b = o >> 1, hp = o & 1;
        float blo, bhi; unpack2(bacc[o], blo, bhi);
        float* base = g_bias + ((size_t)(b*NH + 2*hp)*L + l)*L + m;
        base[0]           = blo;
        base[(size_t)L*L] = bhi;
    }
}

// ---------------- fused QKV (LN + 3 gemms), R=16 rows/CTA, W staged via shared ----------------
__global__ void __launch_bounds__(256)
k_qkv(const float* __restrict__ X, const float* __restrict__ Wq,
      const float* __restrict__ Wk, const float* __restrict__ Wv)
{
    const float* W = (blockIdx.y == 0) ? Wq : (blockIdx.y == 1) ? Wk : Wv;
    float* O = (blockIdx.y == 0) ? g_qm : (blockIdx.y == 1) ? g_km : g_vm;

    constexpr int R = 16;
    __shared__ u64 xs2[R*128];
    __shared__ u64 wst[32*64];       // 32 k-rows x 64 col-pairs = 16KB
    int r0 = blockIdx.x * R;
    int t  = threadIdx.x;

    // LN: 16 threads per row
    {
        int r  = t >> 4, c0 = t & 15;
        const float* xr = X + (size_t)(r0 + r)*128;
        float v[8]; float s = 0.f, ss = 0.f;
        #pragma unroll
        for (int i = 0; i < 8; i++) { v[i] = xr[c0 + i*16]; s += v[i]; ss += v[i]*v[i]; }
        #pragma unroll
        for (int o = 8; o >= 1; o >>= 1) {
            s  += __shfl_xor_sync(0xffffffffu, s,  o);
            ss += __shfl_xor_sync(0xffffffffu, ss, o);
        }
        float mu   = s * (1.f/128.f);
        float rstd = rsqrtf(ss * (1.f/128.f) - mu*mu + 1e-5f);
        #pragma unroll
        for (int i = 0; i < 8; i++) {
            float nv = (v[i] - mu) * rstd;
            xs2[r*128 + c0 + i*16] = pack2(nv, nv);
        }
    }

    int cp = t & 63;
    int g  = t >> 6;
    u64 acc[4] = {0ull, 0ull, 0ull, 0ull};
    const ulonglong2* Wg = (const ulonglong2*)W;      // [128 rows][32 u64-pairs]

    #pragma unroll 1
    for (int kc = 0; kc < 4; kc++) {
        __syncthreads();                               // wst free (and LN done on kc=0)
        // stage W rows [kc*32, kc*32+32): 32x32 ulonglong2 = 1024, 4 per thread
        #pragma unroll
        for (int i = 0; i < 4; i++) {
            int idx = t + i*256;
            int row = idx >> 5, c4 = idx & 31;
            ((ulonglong2*)wst)[row*32 + c4] = Wg[(size_t)(kc*32 + row)*32 + c4];
        }
        __syncthreads();
        #pragma unroll 4
        for (int k2 = 0; k2 < 32; k2++) {
            int k = kc*32 + k2;
            u64 w2 = wst[k2*64 + cp];
            #pragma unroll
            for (int r = 0; r < 4; r++)
                acc[r] = fma2(xs2[(g*4 + r)*128 + k], w2, acc[r]);
        }
    }
    #pragma unroll
    for (int r = 0; r < 4; r++) {
        float lo, hi; unpack2(acc[r], lo, hi);
        float* o = O + (size_t)(r0 + g*4 + r)*128 + 2*cp;
        o[0] = lo; o[1] = hi;
    }
}

// ---------------- attention v3b: 2 queries/thread, reg cap 170 for 3 CTAs/SM ----------------
__global__ void __launch_bounds__(128, 3) k_attn_split(int b)
{
    const float L2E = 1.4426950408889634f;
    const float SCALE_L2E = 0.1767766952966369f * L2E;

    int h  = blockIdx.y;
    int s  = blockIdx.z;
    int q0 = blockIdx.x * 256;
    int t  = threadIdx.x;
    int qa = q0 + t;
    int qb = qa + 128;

    __shared__ alignas(16) float ks[32*32];
    __shared__ alignas(16) float vs[32*32];
    __shared__ float bs[256*33];

    u64 qA[16], qB[16];
    {
        u64 sc2 = pack2(SCALE_L2E, SCALE_L2E);
        const ulonglong2* pa = (const ulonglong2*)(g_qm + (size_t)qa*CA + h*HD);
        const ulonglong2* pb = (const ulonglong2*)(g_qm + (size_t)qb*CA + h*HD);
        #pragma unroll
        for (int i = 0; i < 8; i++) {
            ulonglong2 va = pa[i], vb = pb[i];
            qA[2*i] = mul2(va.x, sc2); qA[2*i+1] = mul2(va.y, sc2);
            qB[2*i] = mul2(vb.x, sc2); qB[2*i+1] = mul2(vb.y, sc2);
        }
    }

    float rmaxA = -1e30f, rmaxB = -1e30f, ssumA = 0.f, ssumB = 0.f;
    u64 accA[16], accB[16];
    #pragma unroll
    for (int i = 0; i < 16; i++) { accA[i] = 0ull; accB[i] = 0ull; }

    const float* bsrc_base = g_bias + ((size_t)(b*NH + h)*L + q0)*L;
    int m_begin = s * (L/KSPLIT);
    int m_end   = m_begin + (L/KSPLIT);

    for (int m0 = m_begin; m0 < m_end; m0 += 32) {
        __syncthreads();
        for (int i = t; i < 256; i += 128) {
            int j = i >> 3, dq = i & 7;
            ((float4*)ks)[i] = ((const float4*)g_km)[(size_t)(m0+j)*32 + h*8 + dq];
            ((float4*)vs)[i] = ((const float4*)g_vm)[(size_t)(m0+j)*32 + h*8 + dq];
        }
        for (int i = t; i < 2048; i += 128) {
            int t2 = i >> 3, jv = i & 7;
            float4 v = *(const float4*)(bsrc_base + (size_t)t2*L + m0 + jv*4);
            float* d = bs + t2*33 + jv*4;
            d[0] = v.x*L2E; d[1] = v.y*L2E; d[2] = v.z*L2E; d[3] = v.w*L2E;
        }
        __syncthreads();

        float tmaxA = -1e30f, tmaxB = -1e30f;
        #pragma unroll 2
        for (int j = 0; j < 32; j++) {
            const ulonglong2* k2 = (const ulonglong2*)(ks + j*32);
            u64 dA0 = pack2(bs[t*33 + j], 0.f);
            u64 dA1 = 0ull;
            u64 dB0 = pack2(bs[(t+128)*33 + j], 0.f);
            u64 dB1 = 0ull;
            #pragma unroll
            for (int i = 0; i < 8; i++) {
                ulonglong2 kk = k2[i];
                dA0 = fma2(qA[2*i],   kk.x, dA0);
                dA1 = fma2(qA[2*i+1], kk.y, dA1);
                dB0 = fma2(qB[2*i],   kk.x, dB0);
                dB1 = fma2(qB[2*i+1], kk.y, dB1);
            }
            u64 dA = add2(dA0, dA1);
            u64 dB = add2(dB0, dB1);
            float a_lo, a_hi, b_lo, b_hi;
            unpack2(dA, a_lo, a_hi);
            unpack2(dB, b_lo, b_hi);
            float la = a_lo + a_hi, lb = b_lo + b_hi;
            bs[t*33 + j]       = la;
            bs[(t+128)*33 + j] = lb;
            tmaxA = fmaxf(tmaxA, la);
            tmaxB = fmaxf(tmaxB, lb);
        }

        {
            float nA = fmaxf(rmaxA, tmaxA);
            float fA = exp2f(rmaxA - nA);
            rmaxA = nA; ssumA *= fA;
            u64 fA2 = pack2(fA, fA);
            float nB = fmaxf(rmaxB, tmaxB);
            float fB = exp2f(rmaxB - nB);
            rmaxB = nB; ssumB *= fB;
            u64 fB2 = pack2(fB, fB);
            #pragma unroll
            for (int i = 0; i < 16; i++) {
                accA[i] = mul2(accA[i], fA2);
                accB[i] = mul2(accB[i], fB2);
            }
        }

        #pragma unroll 2
        for (int j = 0; j < 32; j++) {
            float ea = exp2f(bs[t*33 + j]       - rmaxA);
            float eb = exp2f(bs[(t+128)*33 + j] - rmaxB);
            ssumA += ea;
            ssumB += eb;
            u64 ea2 = pack2(ea, ea);
            u64 eb2 = pack2(eb, eb);
            const ulonglong2* v2 = (const ulonglong2*)(vs + j*32);
            #pragma unroll
            for (int i = 0; i < 8; i++) {
                ulonglong2 vv = v2[i];
                accA[2*i]   = fma2(ea2, vv.x, accA[2*i]);
                accA[2*i+1] = fma2(ea2, vv.y, accA[2*i+1]);
                accB[2*i]   = fma2(eb2, vv.x, accB[2*i]);
                accB[2*i+1] = fma2(eb2, vv.y, accB[2*i+1]);
            }
        }
    }

    {
        int pidx = (s*L + qa)*NH + h;
        g_pmax[pidx] = rmaxA;
        g_psum[pidx] = ssumA;
        u64* pa = (u64*)(g_pacc + (size_t)pidx*HD);
        #pragma unroll
        for (int i = 0; i < 16; i++) pa[i] = accA[i];
    }
    {
        int pidx = (s*L + qb)*NH + h;
        g_pmax[pidx] = rmaxB;
        g_psum[pidx] = ssumB;
        u64* pb = (u64*)(g_pacc + (size_t)pidx*HD);
        #pragma unroll
        for (int i = 0; i < 16; i++) pb[i] = accB[i];
    }
}

// ---------------- fused: comb + Wo + residual + LN + FF1 + FF2 + residual ----------------
__global__ void __launch_bounds__(256)
k_mlp(const float* __restrict__ Wo, const float* __restrict__ Wt1,
      const float* __restrict__ Wt2)
{
    constexpr int R = 8;
    __shared__ u64  xs2 [R*128];
    __shared__ u64  ff2 [R*512];
    __shared__ float qrow[R*128];

    int r0 = blockIdx.x * R;
    int t  = threadIdx.x;

    for (int idx = t; idx < R*128; idx += 256) {
        int row = idx >> 7, c = idx & 127;
        int h = c >> 5, d = c & 31;
        int q = r0 + row;
        float gm = -1e30f;
        #pragma unroll 4
        for (int s = 0; s < KSPLIT; s++)
            gm = fmaxf(gm, g_pmax[(s*L + q)*NH + h]);
        float denom = 0.f, o = 0.f;
        #pragma unroll 4
        for (int s = 0; s < KSPLIT; s++) {
            int pidx = (s*L + q)*NH + h;
            float f = exp2f(g_pmax[pidx] - gm);
            denom += g_psum[pidx] * f;
            o     += g_pacc[(size_t)pidx*HD + d] * f;
        }
        o /= denom;
        xs2[idx] = pack2(o, o);
    }
    __syncthreads();

    {
        int cp = t & 63, g = t >> 6;
        const u64* Wo2 = (const u64*)Wo + cp;
        u64 acc[2] = {0ull, 0ull};
        #pragma unroll 4
        for (int k = 0; k < 128; k++) {
            u64 w2 = Wo2[(size_t)k*64];
            acc[0] = fma2(xs2[(g*2+0)*128 + k], w2, acc[0]);
            acc[1] = fma2(xs2[(g*2+1)*128 + k], w2, acc[1]);
        }
        #pragma unroll
        for (int r = 0; r < 2; r++) {
            int row = g*2 + r;
            int q = r0 + row;
            float lo, hi; unpack2(acc[r], lo, hi);
            lo += g_Q[(size_t)q*128 + 2*cp];
            hi += g_Q[(size_t)q*128 + 2*cp + 1];
            qrow[row*128 + 2*cp]     = lo;
            qrow[row*128 + 2*cp + 1] = hi;
        }
    }
    __syncthreads();

    {
        int w = t >> 5, lane = t & 31;
        float4 v = ((const float4*)(qrow + w*128))[lane];
        float s  = v.x + v.y + v.z + v.w;
        float ss = v.x*v.x + v.y*v.y + v.z*v.z + v.w*v.w;
        #pragma unroll
        for (int o = 16; o >= 1; o >>= 1) {
            s  += __shfl_xor_sync(0xffffffffu, s,  o);
            ss += __shfl_xor_sync(0xffffffffu, ss, o);
        }
        float mu   = s * (1.f/128.f);
        float rstd = rsqrtf(ss * (1.f/128.f) - mu*mu + 1e-5f);
        u64* xd = xs2 + w*128 + lane*4;
        float n0 = (v.x - mu)*rstd, n1 = (v.y - mu)*rstd;
        float n2 = (v.z - mu)*rstd, n3 = (v.w - mu)*rstd;
        xd[0] = pack2(n0, n0); xd[1] = pack2(n1, n1);
        xd[2] = pack2(n2, n2); xd[3] = pack2(n3, n3);
    }
    __syncthreads();

    {
        int cp1 = t;
        const u64* W12 = (const u64*)Wt1 + cp1;
        u64 a1[8];
        #pragma unroll
        for (int r = 0; r < 8; r++) a1[r] = 0ull;
        #pragma unroll 4
        for (int k = 0; k < 128; k++) {
            u64 w2 = W12[(size_t)k*256];
            #pragma unroll
            for (int r = 0; r < 8; r++)
                a1[r] = fma2(xs2[r*128 + k], w2, a1[r]);
        }
        #pragma unroll
        for (int r = 0; r < 8; r++) {
            float lo, hi; unpack2(a1[r], lo, hi);
            lo = fmaxf(lo, 0.f); hi = fmaxf(hi, 0.f);
            ff2[r*512 + 2*cp1]     = pack2(lo, lo);
            ff2[r*512 + 2*cp1 + 1] = pack2(hi, hi);
        }
    }
    __syncthreads();

    {
        int cp = t & 63, g = t >> 6;
        const u64* W22 = (const u64*)Wt2 + cp;
        u64 acc[2] = {0ull, 0ull};
        #pragma unroll 4
        for (int k = 0; k < 512; k++) {
            u64 w2 = W22[(size_t)k*64];
            acc[0] = fma2(ff2[(g*2+0)*512 + k], w2, acc[0]);
            acc[1] = fma2(ff2[(g*2+1)*512 + k], w2, acc[1]);
        }
        #pragma unroll
        for (int r = 0; r < 2; r++) {
            int row = g*2 + r;
            int q = r0 + row;
            float lo, hi; unpack2(acc[r], lo, hi);
            lo += qrow[row*128 + 2*cp];
            hi += qrow[row*128 + 2*cp + 1];
            g_Q[(size_t)q*128 + 2*cp]     = lo;
            g_Q[(size_t)q*128 + 2*cp + 1] = hi;
        }
    }
}

// ---------------- final: copy Q to out + relu(Q @ Wq_tok) ----------------
__global__ void __launch_bounds__(256)
k_out(const float* __restrict__ X, const float* __restrict__ W,
      float* __restrict__ OUT, float* __restrict__ outQ)
{
    constexpr int R = 16;
    constexpr int NSUB = 128;
    __shared__ u64 xs2[R*128];
    int r0 = blockIdx.x * R;
    int t  = threadIdx.x;
    int colOff = blockIdx.y * NSUB;

    {
        const float* xb = X + (size_t)r0*128;
        float* qb = outQ + (size_t)r0*128;
        bool docopy = (blockIdx.y == 0);
        for (int i = t; i < R*128; i += 256) {
            float v = xb[i];
            xs2[i] = pack2(v, v);
            if (docopy) qb[i] = v;
        }
    }
    __syncthreads();

    int cp = t & 63, g = t >> 6;
    const u64* Wp = (const u64*)W + (colOff >> 1) + cp;
    u64 acc[4] = {0ull, 0ull, 0ull, 0ull};
    #pragma unroll 4
    for (int k = 0; k < 128; k++) {
        u64 w2 = Wp[(size_t)k*(CT/2)];
        #pragma unroll
        for (int r = 0; r < 4; r++)
            acc[r] = fma2(xs2[(g*4 + r)*128 + k], w2, acc[r]);
    }
    #pragma unroll
    for (int r = 0; r < 4; r++) {
        float lo, hi; unpack2(acc[r], lo, hi);
        lo = fmaxf(lo, 0.f); hi = fmaxf(hi, 0.f);
        float* o = OUT + (size_t)(r0 + g*4 + r)*CT + colOff + 2*cp;
        o[0] = lo; o[1] = hi;
    }
}

// ---------------- segment mean ----------------
__global__ void k_seg(const float* __restrict__ pQ, const int* __restrict__ tok,
                      float* __restrict__ outA)
{
    __shared__ int slo, shi;
    int i = blockIdx.x;
    if (threadIdx.x == 0) {
        int lo = 0, hi = L;
        while (lo < hi) { int mid = (lo+hi) >> 1; if (tok[mid] < i) lo = mid+1; else hi = mid; }
        slo = lo;
        int lo2 = lo, hi2 = L;
        while (lo2 < hi2) { int mid = (lo2+hi2) >> 1; if (tok[mid] < i+1) lo2 = mid+1; else hi2 = mid; }
        shi = lo2;
    }
    __syncthreads();
    int lo = slo, hi = shi;
    float inv = (hi > lo) ? 1.f/(float)(hi - lo) : 0.f;
    int c = threadIdx.x;
    float a = 0.f;
    for (int at = lo; at < hi; at++) a += pQ[(size_t)at*CT + c];
    outA[(size_t)i*CT + c] = a * inv;
}

// ---------------- launch ----------------
extern "C" void kernel_launch(void* const* d_in, const int* in_sizes, int n_in,
                              void* d_out, int out_size)
{
    const float* pos    = (const float*)d_in[0];
    const float* charge = (const float*)d_in[1];
    const float* elem   = (const float*)d_in[2];
    const float* chars  = (const float*)d_in[3];
    const int*   uid    = (const int*)  d_in[4];
    const int*   tok    = (const int*)  d_in[5];
    const float* Win    = (const float*)d_in[6];
    const float* Wd     = (const float*)d_in[7];
    const float* Wiv    = (const float*)d_in[8];
    const float* Wvmw   = (const float*)d_in[9];
    const float* Wsl    = (const float*)d_in[10];
    const float* Wsm    = (const float*)d_in[11];
    const float* Wp1    = (const float*)d_in[12];
    const float* Wp2    = (const float*)d_in[13];
    const float* Wp3    = (const float*)d_in[14];
    const float* Wqtok  = (const float*)d_in[15];
    const float* Wq     = (const float*)d_in[16];
    const float* Wk     = (const float*)d_in[17];
    const float* Wv     = (const float*)d_in[18];
    const float* Wb     = (const float*)d_in[19];
    const float* Wo     = (const float*)d_in[20];
    const float* Wt1    = (const float*)d_in[21];
    const float* Wt2    = (const float*)d_in[22];

    float* out   = (float*)d_out;
    float* outA  = out + OFF_A;
    float* outQ  = out + OFF_Q;
    float* outCL = out + OFF_CL;
    float* outP  = out + OFF_P;

    float *pQbuf, *pFF;
    cudaGetSymbolAddress((void**)&pQbuf, g_Q);
    cudaGetSymbolAddress((void**)&pFF,   g_ff);

    k_cl  <<<L, 128>>>(pos, charge, elem, chars, Win, Wsl, Wsm, outCL);
    k_pair<<<dim3(8, L), 256>>>(pos, uid, Wd, Wiv, Wvmw, Wp1, Wp2, Wp3, Wb, outP);

    for (int b = 0; b < NBLK; b++) {
        k_qkv<<<dim3(L/16, 3), 256>>>(pQbuf, Wq + (size_t)b*CA*CA,
                                      Wk + (size_t)b*CA*CA, Wv + (size_t)b*CA*CA);
        k_attn_split<<<dim3(L/256, NH, KSPLIT), 128>>>(b);
        k_mlp<<<L/8, 256>>>(Wo + (size_t)b*CA*CA, Wt1 + (size_t)b*CA*FFDIM,
                            Wt2 + (size_t)b*FFDIM*CA);
    }

    k_out<<<dim3(L/16, 3), 256>>>(pQbuf, Wqtok, pFF, outQ);
    k_seg<<<TOKS, CT>>>(pFF, tok, outA);
}

// round 17
// speedup vs baseline: 1.1112x; 1.0019x over previous
#include <cuda_runtime.h>
#include <math.h>

#define L 2048
#define TOKS 512
#define CA 128
#define CP 16
#define CT 384
#define NH 4
#define HD 32
#define FFDIM 512
#define NBLK 3
#define F1D 388
#define KSPLIT 32

#define OFF_A 0
#define OFF_Q (TOKS*CT)
#define OFF_CL (OFF_Q + L*CA)
#define OFF_P (OFF_CL + L*CA)

typedef unsigned long long u64;

// ---------------- f32x2 helpers ----------------
__device__ __forceinline__ u64 pack2(float lo, float hi) {
    u64 r; asm("mov.b64 %0, {%1, %2};" : "=l"(r) : "f"(lo), "f"(hi)); return r;
}
__device__ __forceinline__ void unpack2(u64 v, float& lo, float& hi) {
    asm("mov.b64 {%0, %1}, %2;" : "=f"(lo), "=f"(hi) : "l"(v));
}
__device__ __forceinline__ u64 fma2(u64 a, u64 b, u64 c) {
    u64 d; asm("fma.rn.f32x2 %0, %1, %2, %3;" : "=l"(d) : "l"(a), "l"(b), "l"(c)); return d;
}
__device__ __forceinline__ u64 mul2(u64 a, u64 b) {
    u64 d; asm("mul.rn.f32x2 %0, %1, %2;" : "=l"(d) : "l"(a), "l"(b)); return d;
}
__device__ __forceinline__ u64 add2(u64 a, u64 b) {
    u64 d; asm("add.rn.f32x2 %0, %1, %2;" : "=l"(d) : "l"(a), "l"(b)); return d;
}
__device__ __forceinline__ u64 relu2(u64 v) {
    float lo, hi; unpack2(v, lo, hi);
    return pack2(fmaxf(lo, 0.f), fmaxf(hi, 0.f));
}

// ---------------- scratch ----------------
__device__ float g_Q  [L*CA];
__device__ float g_qm [L*CA];
__device__ float g_km [L*CA];
__device__ float g_vm [L*CA];
__device__ float g_ff [L*FFDIM];
__device__ float g_sl [L*CP];
__device__ float g_sm [L*CP];
__device__ float g_bias[(size_t)NBLK*NH*L*L];           // [b][h][l][m]
__device__ float g_pmax[KSPLIT*L*NH];
__device__ float g_psum[KSPLIT*L*NH];
__device__ float g_pacc[(size_t)KSPLIT*L*NH*HD];

// ---------------- C_L = concat(feat)@W_in ; seeds Q ; fused sl/sm projections ----------------
__global__ void k_cl(const float* __restrict__ pos, const float* __restrict__ charge,
                     const float* __restrict__ elem, const float* __restrict__ chars,
                     const float* __restrict__ Win, const float* __restrict__ Wsl,
                     const float* __restrict__ Wsm, float* __restrict__ outCL)
{
    __shared__ float f[F1D];
    __shared__ float r[128];
    int l = blockIdx.x, t = threadIdx.x;
    if (t < 3)  f[t]   = pos[l*3 + t];
    if (t == 3) f[3]   = charge[l];
    f[4   + t] = elem [l*128 + t];
    f[132 + t] = chars[l*256 + t];
    f[260 + t] = chars[l*256 + 128 + t];
    __syncthreads();
    float acc = 0.f;
    #pragma unroll 4
    for (int k = 0; k < F1D; k++) acc += f[k] * Win[(size_t)k*CA + t];
    outCL[(size_t)l*CA + t] = acc;
    g_Q  [(size_t)l*CA + t] = acc;
    r[t] = fmaxf(acc, 0.f);
    __syncthreads();
    if (t < 16) {
        float a = 0.f;
        #pragma unroll 4
        for (int k = 0; k < 128; k++) a += r[k] * Wsl[k*16 + t];
        g_sl[l*16 + t] = a;
    } else if (t < 32) {
        int c = t - 16;
        float a = 0.f;
        #pragma unroll 4
        for (int k = 0; k < 128; k++) a += r[k] * Wsm[k*16 + c];
        g_sm[l*16 + c] = a;
    }
}

// ---------------- pair: channel-packed f32x2, fused relu+splat, LDS.128 weights ----------------
__global__ void __launch_bounds__(256, 3)
k_pair(const float* __restrict__ pos, const int* __restrict__ uid,
       const float* __restrict__ Wd,  const float* __restrict__ Wiv,
       const float* __restrict__ Wvm, const float* __restrict__ Wp1,
       const float* __restrict__ Wp2, const float* __restrict__ Wp3,
       const float* __restrict__ Wb,  float* __restrict__ outP)
{
    __shared__ alignas(16) u64 w1[128], w2[128], w3[128], wb2[96];
    __shared__ u64 wd2[24], wiv2[8], wvm2[8], sl2[8];
    __shared__ float pl[3];
    __shared__ int ul;
    int l = blockIdx.y;
    int t = threadIdx.x;
    int m = blockIdx.x*256 + t;

    if (t < 128) {
        w1[t] = ((const u64*)Wp1)[t];
        w3[t] = ((const u64*)Wp3)[t];
    } else {
        int u = t - 128;
        w2[u] = ((const u64*)Wp2)[u];
    }
    if (t < 24)                wd2[t]     = ((const u64*)Wd)[t];
    else if (t < 32)           wiv2[t-24] = ((const u64*)Wiv)[t-24];
    else if (t < 40)           wvm2[t-32] = ((const u64*)Wvm)[t-32];
    else if (t >= 40 && t < 136) wb2[t-40] = ((const u64*)Wb)[t-40];
    if (t >= 136 && t < 144)   sl2[t-136] = ((const u64*)(g_sl + l*16))[t-136];
    if (t >= 144 && t < 147)   pl[t-144]  = pos[l*3 + (t-144)];
    if (t == 147)              ul = uid[l];

    float mx = pos[m*3+0], my = pos[m*3+1], mz = pos[m*3+2];
    int   um = uid[m];
    __syncthreads();

    float d0 = pl[0] - mx, d1 = pl[1] - my, d2 = pl[2] - mz;
    float iv = 1.f / (1.f + sqrtf(d0*d0 + d1*d1 + d2*d2));
    float vf = (ul == um) ? 1.f : 0.f;
    u64 d0s = pack2(d0, d0), d1s = pack2(d1, d1), d2s = pack2(d2, d2);
    u64 ivs = pack2(iv, iv), vfs = pack2(vf, vf);

    u64 p[8];
    {
        const ulonglong2* smp = (const ulonglong2*)(g_sm + (size_t)m*16);
        #pragma unroll
        for (int i = 0; i < 4; i++) {
            ulonglong2 sm2v = smp[i];
            u64 t0 = wvm2[2*i];
            t0 = fma2(ivs, wiv2[2*i],    t0);
            t0 = fma2(d2s, wd2[16+2*i],  t0);
            t0 = fma2(d1s, wd2[8+2*i],   t0);
            t0 = fma2(d0s, wd2[2*i],     t0);
            p[2*i]   = fma2(vfs, t0, add2(sl2[2*i], sm2v.x));
            u64 t1 = wvm2[2*i+1];
            t1 = fma2(ivs, wiv2[2*i+1],   t1);
            t1 = fma2(d2s, wd2[16+2*i+1], t1);
            t1 = fma2(d1s, wd2[8+2*i+1],  t1);
            t1 = fma2(d0s, wd2[2*i+1],    t1);
            p[2*i+1] = fma2(vfs, t1, add2(sl2[2*i+1], sm2v.y));
        }
    }

    const ulonglong2* wv1 = (const ulonglong2*)w1;
    const ulonglong2* wv2 = (const ulonglong2*)w2;
    const ulonglong2* wv3 = (const ulonglong2*)w3;
    u64 a[8], c[8];

    // ---- layer 1: a = splat(relu(p)) @ W1 (relu folded into splat; LDS.128 weights) ----
    #pragma unroll
    for (int i = 0; i < 8; i++) a[i] = 0ull;
    #pragma unroll
    for (int jj = 0; jj < 8; jj++) {
        float lo, hi; unpack2(p[jj], lo, hi);
        lo = fmaxf(lo, 0.f); hi = fmaxf(hi, 0.f);
        u64 s0 = pack2(lo, lo), s1 = pack2(hi, hi);
        #pragma unroll
        for (int ip = 0; ip < 4; ip++) {
            ulonglong2 w = wv1[(2*jj)*4 + ip];
            a[2*ip]   = fma2(s0, w.x, a[2*ip]);
            a[2*ip+1] = fma2(s0, w.y, a[2*ip+1]);
        }
        #pragma unroll
        for (int ip = 0; ip < 4; ip++) {
            ulonglong2 w = wv1[(2*jj+1)*4 + ip];
            a[2*ip]   = fma2(s1, w.x, a[2*ip]);
            a[2*ip+1] = fma2(s1, w.y, a[2*ip+1]);
        }
    }
    // ---- layer 2: c = splat(relu(a)) @ W2 ----
    #pragma unroll
    for (int i = 0; i < 8; i++) c[i] = 0ull;
    #pragma unroll
    for (int jj = 0; jj < 8; jj++) {
        float lo, hi; unpack2(a[jj], lo, hi);
        lo = fmaxf(lo, 0.f); hi = fmaxf(hi, 0.f);
        u64 s0 = pack2(lo, lo), s1 = pack2(hi, hi);
        #pragma unroll
        for (int ip = 0; ip < 4; ip++) {
            ulonglong2 w = wv2[(2*jj)*4 + ip];
            c[2*ip]   = fma2(s0, w.x, c[2*ip]);
            c[2*ip+1] = fma2(s0, w.y, c[2*ip+1]);
        }
        #pragma unroll
        for (int ip = 0; ip < 4; ip++) {
            ulonglong2 w = wv2[(2*jj+1)*4 + ip];
            c[2*ip]   = fma2(s1, w.x, c[2*ip]);
            c[2*ip+1] = fma2(s1, w.y, c[2*ip+1]);
        }
    }
    // ---- layer 3: a = splat(relu(c)) @ W3 ; p += a ----
    #pragma unroll
    for (int i = 0; i < 8; i++) a[i] = 0ull;
    #pragma unroll
    for (int jj = 0; jj < 8; jj++) {
        float lo, hi; unpack2(c[jj], lo, hi);
        lo = fmaxf(lo, 0.f); hi = fmaxf(hi, 0.f);
        u64 s0 = pack2(lo, lo), s1 = pack2(hi, hi);
        #pragma unroll
        for (int ip = 0; ip < 4; ip++) {
            ulonglong2 w = wv3[(2*jj)*4 + ip];
            a[2*ip]   = fma2(s0, w.x, a[2*ip]);
            a[2*ip+1] = fma2(s0, w.y, a[2*ip+1]);
        }
        #pragma unroll
        for (int ip = 0; ip < 4; ip++) {
            ulonglong2 w = wv3[(2*jj+1)*4 + ip];
            a[2*ip]   = fma2(s1, w.x, a[2*ip]);
            a[2*ip+1] = fma2(s1, w.y, a[2*ip+1]);
        }
    }
    #pragma unroll
    for (int i = 0; i < 8; i++) p[i] = add2(p[i], a[i]);

    // store P row
    {
        ulonglong2* dst = (ulonglong2*)(outP + ((size_t)l*L + m)*16);
        #pragma unroll
        for (int i = 0; i < 4; i++) {
            ulonglong2 v; v.x = p[2*i]; v.y = p[2*i+1];
            dst[i] = v;
        }
    }

    // bias: 3 blocks x 2 head-pairs, splat on-the-fly, LDS.128 weights
    const ulonglong2* wvb = (const ulonglong2*)wb2;
    u64 bacc[6];
    #pragma unroll
    for (int o = 0; o < 6; o++) bacc[o] = 0ull;
    #pragma unroll
    for (int jj = 0; jj < 8; jj++) {
        float lo, hi; unpack2(p[jj], lo, hi);
        u64 s0 = pack2(lo, lo), s1 = pack2(hi, hi);
        #pragma unroll
        for (int bb = 0; bb < 3; bb++) {
            ulonglong2 w = wvb[bb*16 + 2*jj];
            bacc[bb*2]   = fma2(s0, w.x, bacc[bb*2]);
            bacc[bb*2+1] = fma2(s0, w.y, bacc[bb*2+1]);
        }
        #pragma unroll
        for (int bb = 0; bb < 3; bb++) {
            ulonglong2 w = wvb[bb*16 + 2*jj + 1];
            bacc[bb*2]   = fma2(s1, w.x, bacc[bb*2]);
            bacc[bb*2+1] = fma2(s1, w.y, bacc[bb*2+1]);
        }
    }
    #pragma unroll
    for (int o = 0; o < 6; o++) {
        int b = o >> 1, hp = o & 1;
        float blo, bhi; unpack2(bacc[o], blo, bhi);
        float* base = g_bias + ((size_t)(b*NH + 2*hp)*L + l)*L + m;
        base[0]           = blo;
        base[(size_t)L*L] = bhi;
    }
}

// ---------------- fused QKV (LN + 3 gemms), R=16 rows/CTA, W staged via shared ----------------
__global__ void __launch_bounds__(256)
k_qkv(const float* __restrict__ X, const float* __restrict__ Wq,
      const float* __restrict__ Wk, const float* __restrict__ Wv)
{
    const float* W = (blockIdx.y == 0) ? Wq : (blockIdx.y == 1) ? Wk : Wv;
    float* O = (blockIdx.y == 0) ? g_qm : (blockIdx.y == 1) ? g_km : g_vm;

    constexpr int R = 16;
    __shared__ u64 xs2[R*128];
    __shared__ u64 wst[32*64];       // 32 k-rows x 64 col-pairs = 16KB
    int r0 = blockIdx.x * R;
    int t  = threadIdx.x;

    // LN: 16 threads per row
    {
        int r  = t >> 4, c0 = t & 15;
        const float* xr = X + (size_t)(r0 + r)*128;
        float v[8]; float s = 0.f, ss = 0.f;
        #pragma unroll
        for (int i = 0; i < 8; i++) { v[i] = xr[c0 + i*16]; s += v[i]; ss += v[i]*v[i]; }
        #pragma unroll
        for (int o = 8; o >= 1; o >>= 1) {
            s  += __shfl_xor_sync(0xffffffffu, s,  o);
            ss += __shfl_xor_sync(0xffffffffu, ss, o);
        }
        float mu   = s * (1.f/128.f);
        float rstd = rsqrtf(ss * (1.f/128.f) - mu*mu + 1e-5f);
        #pragma unroll
        for (int i = 0; i < 8; i++) {
            float nv = (v[i] - mu) * rstd;
            xs2[r*128 + c0 + i*16] = pack2(nv, nv);
        }
    }

    int cp = t & 63;
    int g  = t >> 6;
    u64 acc[4] = {0ull, 0ull, 0ull, 0ull};
    const ulonglong2* Wg = (const ulonglong2*)W;

    #pragma unroll 1
    for (int kc = 0; kc < 4; kc++) {
        __syncthreads();
        #pragma unroll
        for (int i = 0; i < 4; i++) {
            int idx = t + i*256;
            int row = idx >> 5, c4 = idx & 31;
            ((ulonglong2*)wst)[row*32 + c4] = Wg[(size_t)(kc*32 + row)*32 + c4];
        }
        __syncthreads();
        #pragma unroll 4
        for (int k2 = 0; k2 < 32; k2++) {
            int k = kc*32 + k2;
            u64 w2 = wst[k2*64 + cp];
            #pragma unroll
            for (int r = 0; r < 4; r++)
                acc[r] = fma2(xs2[(g*4 + r)*128 + k], w2, acc[r]);
        }
    }
    #pragma unroll
    for (int r = 0; r < 4; r++) {
        float lo, hi; unpack2(acc[r], lo, hi);
        float* o = O + (size_t)(r0 + g*4 + r)*128 + 2*cp;
        o[0] = lo; o[1] = hi;
    }
}

// ---------------- attention v3b: 2 queries/thread, reg cap 170 for 3 CTAs/SM ----------------
__global__ void __launch_bounds__(128, 3) k_attn_split(int b)
{
    const float L2E = 1.4426950408889634f;
    const float SCALE_L2E = 0.1767766952966369f * L2E;

    int h  = blockIdx.y;
    int s  = blockIdx.z;
    int q0 = blockIdx.x * 256;
    int t  = threadIdx.x;
    int qa = q0 + t;
    int qb = qa + 128;

    __shared__ alignas(16) float ks[32*32];
    __shared__ alignas(16) float vs[32*32];
    __shared__ float bs[256*33];

    u64 qA[16], qB[16];
    {
        u64 sc2 = pack2(SCALE_L2E, SCALE_L2E);
        const ulonglong2* pa = (const ulonglong2*)(g_qm + (size_t)qa*CA + h*HD);
        const ulonglong2* pb = (const ulonglong2*)(g_qm + (size_t)qb*CA + h*HD);
        #pragma unroll
        for (int i = 0; i < 8; i++) {
            ulonglong2 va = pa[i], vb = pb[i];
            qA[2*i] = mul2(va.x, sc2); qA[2*i+1] = mul2(va.y, sc2);
            qB[2*i] = mul2(vb.x, sc2); qB[2*i+1] = mul2(vb.y, sc2);
        }
    }

    float rmaxA = -1e30f, rmaxB = -1e30f, ssumA = 0.f, ssumB = 0.f;
    u64 accA[16], accB[16];
    #pragma unroll
    for (int i = 0; i < 16; i++) { accA[i] = 0ull; accB[i] = 0ull; }

    const float* bsrc_base = g_bias + ((size_t)(b*NH + h)*L + q0)*L;
    int m_begin = s * (L/KSPLIT);
    int m_end   = m_begin + (L/KSPLIT);

    for (int m0 = m_begin; m0 < m_end; m0 += 32) {
        __syncthreads();
        for (int i = t; i < 256; i += 128) {
            int j = i >> 3, dq = i & 7;
            ((float4*)ks)[i] = ((const float4*)g_km)[(size_t)(m0+j)*32 + h*8 + dq];
            ((float4*)vs)[i] = ((const float4*)g_vm)[(size_t)(m0+j)*32 + h*8 + dq];
        }
        for (int i = t; i < 2048; i += 128) {
            int t2 = i >> 3, jv = i & 7;
            float4 v = *(const float4*)(bsrc_base + (size_t)t2*L + m0 + jv*4);
            float* d = bs + t2*33 + jv*4;
            d[0] = v.x*L2E; d[1] = v.y*L2E; d[2] = v.z*L2E; d[3] = v.w*L2E;
        }
        __syncthreads();

        float tmaxA = -1e30f, tmaxB = -1e30f;
        #pragma unroll 2
        for (int j = 0; j < 32; j++) {
            const ulonglong2* k2 = (const ulonglong2*)(ks + j*32);
            u64 dA0 = pack2(bs[t*33 + j], 0.f);
            u64 dA1 = 0ull;
            u64 dB0 = pack2(bs[(t+128)*33 + j], 0.f);
            u64 dB1 = 0ull;
            #pragma unroll
            for (int i = 0; i < 8; i++) {
                ulonglong2 kk = k2[i];
                dA0 = fma2(qA[2*i],   kk.x, dA0);
                dA1 = fma2(qA[2*i+1], kk.y, dA1);
                dB0 = fma2(qB[2*i],   kk.x, dB0);
                dB1 = fma2(qB[2*i+1], kk.y, dB1);
            }
            u64 dA = add2(dA0, dA1);
            u64 dB = add2(dB0, dB1);
            float a_lo, a_hi, b_lo, b_hi;
            unpack2(dA, a_lo, a_hi);
            unpack2(dB, b_lo, b_hi);
            float la = a_lo + a_hi, lb = b_lo + b_hi;
            bs[t*33 + j]       = la;
            bs[(t+128)*33 + j] = lb;
            tmaxA = fmaxf(tmaxA, la);
            tmaxB = fmaxf(tmaxB, lb);
        }

        {
            float nA = fmaxf(rmaxA, tmaxA);
            float fA = exp2f(rmaxA - nA);
            rmaxA = nA; ssumA *= fA;
            u64 fA2 = pack2(fA, fA);
            float nB = fmaxf(rmaxB, tmaxB);
            float fB = exp2f(rmaxB - nB);
            rmaxB = nB; ssumB *= fB;
            u64 fB2 = pack2(fB, fB);
            #pragma unroll
            for (int i = 0; i < 16; i++) {
                accA[i] = mul2(accA[i], fA2);
                accB[i] = mul2(accB[i], fB2);
            }
        }

        #pragma unroll 2
        for (int j = 0; j < 32; j++) {
            float ea = exp2f(bs[t*33 + j]       - rmaxA);
            float eb = exp2f(bs[(t+128)*33 + j] - rmaxB);
            ssumA += ea;
            ssumB += eb;
            u64 ea2 = pack2(ea, ea);
            u64 eb2 = pack2(eb, eb);
            const ulonglong2* v2 = (const ulonglong2*)(vs + j*32);
            #pragma unroll
            for (int i = 0; i < 8; i++) {
                ulonglong2 vv = v2[i];
                accA[2*i]   = fma2(ea2, vv.x, accA[2*i]);
                accA[2*i+1] = fma2(ea2, vv.y, accA[2*i+1]);
                accB[2*i]   = fma2(eb2, vv.x, accB[2*i]);
                accB[2*i+1] = fma2(eb2, vv.y, accB[2*i+1]);
            }
        }
    }

    {
        int pidx = (s*L + qa)*NH + h;
        g_pmax[pidx] = rmaxA;
        g_psum[pidx] = ssumA;
        u64* pa = (u64*)(g_pacc + (size_t)pidx*HD);
        #pragma unroll
        for (int i = 0; i < 16; i++) pa[i] = accA[i];
    }
    {
        int pidx = (s*L + qb)*NH + h;
        g_pmax[pidx] = rmaxB;
        g_psum[pidx] = ssumB;
        u64* pb = (u64*)(g_pacc + (size_t)pidx*HD);
        #pragma unroll
        for (int i = 0; i < 16; i++) pb[i] = accB[i];
    }
}

// ---------------- fused: comb + Wo + residual + LN + FF1 + FF2 + residual ----------------
__global__ void __launch_bounds__(256)
k_mlp(const float* __restrict__ Wo, const float* __restrict__ Wt1,
      const float* __restrict__ Wt2)
{
    constexpr int R = 8;
    __shared__ u64  xs2 [R*128];
    __shared__ u64  ff2 [R*512];
    __shared__ float qrow[R*128];

    int r0 = blockIdx.x * R;
    int t  = threadIdx.x;

    for (int idx = t; idx < R*128; idx += 256) {
        int row = idx >> 7, c = idx & 127;
        int h = c >> 5, d = c & 31;
        int q = r0 + row;
        float gm = -1e30f;
        #pragma unroll 4
        for (int s = 0; s < KSPLIT; s++)
            gm = fmaxf(gm, g_pmax[(s*L + q)*NH + h]);
        float denom = 0.f, o = 0.f;
        #pragma unroll 4
        for (int s = 0; s < KSPLIT; s++) {
            int pidx = (s*L + q)*NH + h;
            float f = exp2f(g_pmax[pidx] - gm);
            denom += g_psum[pidx] * f;
            o     += g_pacc[(size_t)pidx*HD + d] * f;
        }
        o /= denom;
        xs2[idx] = pack2(o, o);
    }
    __syncthreads();

    {
        int cp = t & 63, g = t >> 6;
        const u64* Wo2 = (const u64*)Wo + cp;
        u64 acc[2] = {0ull, 0ull};
        #pragma unroll 4
        for (int k = 0; k < 128; k++) {
            u64 w2 = Wo2[(size_t)k*64];
            acc[0] = fma2(xs2[(g*2+0)*128 + k], w2, acc[0]);
            acc[1] = fma2(xs2[(g*2+1)*128 + k], w2, acc[1]);
        }
        #pragma unroll
        for (int r = 0; r < 2; r++) {
            int row = g*2 + r;
            int q = r0 + row;
            float lo, hi; unpack2(acc[r], lo, hi);
            lo += g_Q[(size_t)q*128 + 2*cp];
            hi += g_Q[(size_t)q*128 + 2*cp + 1];
            qrow[row*128 + 2*cp]     = lo;
            qrow[row*128 + 2*cp + 1] = hi;
        }
    }
    __syncthreads();

    {
        int w = t >> 5, lane = t & 31;
        float4 v = ((const float4*)(qrow + w*128))[lane];
        float s  = v.x + v.y + v.z + v.w;
        float ss = v.x*v.x + v.y*v.y + v.z*v.z + v.w*v.w;
        #pragma unroll
        for (int o = 16; o >= 1; o >>= 1) {
            s  += __shfl_xor_sync(0xffffffffu, s,  o);
            ss += __shfl_xor_sync(0xffffffffu, ss, o);
        }
        float mu   = s * (1.f/128.f);
        float rstd = rsqrtf(ss * (1.f/128.f) - mu*mu + 1e-5f);
        u64* xd = xs2 + w*128 + lane*4;
        float n0 = (v.x - mu)*rstd, n1 = (v.y - mu)*rstd;
        float n2 = (v.z - mu)*rstd, n3 = (v.w - mu)*rstd;
        xd[0] = pack2(n0, n0); xd[1] = pack2(n1, n1);
        xd[2] = pack2(n2, n2); xd[3] = pack2(n3, n3);
    }
    __syncthreads();

    {
        int cp1 = t;
        const u64* W12 = (const u64*)Wt1 + cp1;
        u64 a1[8];
        #pragma unroll
        for (int r = 0; r < 8; r++) a1[r] = 0ull;
        #pragma unroll 4
        for (int k = 0; k < 128; k++) {
            u64 w2 = W12[(size_t)k*256];
            #pragma unroll
            for (int r = 0; r < 8; r++)
                a1[r] = fma2(xs2[r*128 + k], w2, a1[r]);
        }
        #pragma unroll
        for (int r = 0; r < 8; r++) {
            float lo, hi; unpack2(a1[r], lo, hi);
            lo = fmaxf(lo, 0.f); hi = fmaxf(hi, 0.f);
            ff2[r*512 + 2*cp1]     = pack2(lo, lo);
            ff2[r*512 + 2*cp1 + 1] = pack2(hi, hi);
        }
    }
    __syncthreads();

    {
        int cp = t & 63, g = t >> 6;
        const u64* W22 = (const u64*)Wt2 + cp;
        u64 acc[2] = {0ull, 0ull};
        #pragma unroll 4
        for (int k = 0; k < 512; k++) {
            u64 w2 = W22[(size_t)k*64];
            acc[0] = fma2(ff2[(g*2+0)*512 + k], w2, acc[0]);
            acc[1] = fma2(ff2[(g*2+1)*512 + k], w2, acc[1]);
        }
        #pragma unroll
        for (int r = 0; r < 2; r++) {
            int row = g*2 + r;
            int q = r0 + row;
            float lo, hi; unpack2(acc[r], lo, hi);
            lo += qrow[row*128 + 2*cp];
            hi += qrow[row*128 + 2*cp + 1];
            g_Q[(size_t)q*128 + 2*cp]     = lo;
            g_Q[(size_t)q*128 + 2*cp + 1] = hi;
        }
    }
}

// ---------------- final: copy Q to out + relu(Q @ Wq_tok) ----------------
__global__ void __launch_bounds__(256)
k_out(const float* __restrict__ X, const float* __restrict__ W,
      float* __restrict__ OUT, float* __restrict__ outQ)
{
    constexpr int R = 16;
    constexpr int NSUB = 128;
    __shared__ u64 xs2[R*128];
    int r0 = blockIdx.x * R;
    int t  = threadIdx.x;
    int colOff = blockIdx.y * NSUB;

    {
        const float* xb = X + (size_t)r0*128;
        float* qb = outQ + (size_t)r0*128;
        bool docopy = (blockIdx.y == 0);
        for (int i = t; i < R*128; i += 256) {
            float v = xb[i];
            xs2[i] = pack2(v, v);
            if (docopy) qb[i] = v;
        }
    }
    __syncthreads();

    int cp = t & 63, g = t >> 6;
    const u64* Wp = (const u64*)W + (colOff >> 1) + cp;
    u64 acc[4] = {0ull, 0ull, 0ull, 0ull};
    #pragma unroll 4
    for (int k = 0; k < 128; k++) {
        u64 w2 = Wp[(size_t)k*(CT/2)];
        #pragma unroll
        for (int r = 0; r < 4; r++)
            acc[r] = fma2(xs2[(g*4 + r)*128 + k], w2, acc[r]);
    }
    #pragma unroll
    for (int r = 0; r < 4; r++) {
        float lo, hi; unpack2(acc[r], lo, hi);
        lo = fmaxf(lo, 0.f); hi = fmaxf(hi, 0.f);
        float* o = OUT + (size_t)(r0 + g*4 + r)*CT + colOff + 2*cp;
        o[0] = lo; o[1] = hi;
    }
}

// ---------------- segment mean ----------------
__global__ void k_seg(const float* __restrict__ pQ, const int* __restrict__ tok,
                      float* __restrict__ outA)
{
    __shared__ int slo, shi;
    int i = blockIdx.x;
    if (threadIdx.x == 0) {
        int lo = 0, hi = L;
        while (lo < hi) { int mid = (lo+hi) >> 1; if (tok[mid] < i) lo = mid+1; else hi = mid; }
        slo = lo;
        int lo2 = lo, hi2 = L;
        while (lo2 < hi2) { int mid = (lo2+hi2) >> 1; if (tok[mid] < i+1) lo2 = mid+1; else hi2 = mid; }
        shi = lo2;
    }
    __syncthreads();
    int lo = slo, hi = shi;
    float inv = (hi > lo) ? 1.f/(float)(hi - lo) : 0.f;
    int c = threadIdx.x;
    float a = 0.f;
    for (int at = lo; at < hi; at++) a += pQ[(size_t)at*CT + c];
    outA[(size_t)i*CT + c] = a * inv;
}

// ---------------- launch ----------------
extern "C" void kernel_launch(void* const* d_in, const int* in_sizes, int n_in,
                              void* d_out, int out_size)
{
    const float* pos    = (const float*)d_in[0];
    const float* charge = (const float*)d_in[1];
    const float* elem   = (const float*)d_in[2];
    const float* chars  = (const float*)d_in[3];
    const int*   uid    = (const int*)  d_in[4];
    const int*   tok    = (const int*)  d_in[5];
    const float* Win    = (const float*)d_in[6];
    const float* Wd     = (const float*)d_in[7];
    const float* Wiv    = (const float*)d_in[8];
    const float* Wvmw   = (const float*)d_in[9];
    const float* Wsl    = (const float*)d_in[10];
    const float* Wsm    = (const float*)d_in[11];
    const float* Wp1    = (const float*)d_in[12];
    const float* Wp2    = (const float*)d_in[13];
    const float* Wp3    = (const float*)d_in[14];
    const float* Wqtok  = (const float*)d_in[15];
    const float* Wq     = (const float*)d_in[16];
    const float* Wk     = (const float*)d_in[17];
    const float* Wv     = (const float*)d_in[18];
    const float* Wb     = (const float*)d_in[19];
    const float* Wo     = (const float*)d_in[20];
    const float* Wt1    = (const float*)d_in[21];
    const float* Wt2    = (const float*)d_in[22];

    float* out   = (float*)d_out;
    float* outA  = out + OFF_A;
    float* outQ  = out + OFF_Q;
    float* outCL = out + OFF_CL;
    float* outP  = out + OFF_P;

    float *pQbuf, *pFF;
    cudaGetSymbolAddress((void**)&pQbuf, g_Q);
    cudaGetSymbolAddress((void**)&pFF,   g_ff);

    k_cl  <<<L, 128>>>(pos, charge, elem, chars, Win, Wsl, Wsm, outCL);
    k_pair<<<dim3(8, L), 256>>>(pos, uid, Wd, Wiv, Wvmw, Wp1, Wp2, Wp3, Wb, outP);

    for (int b = 0; b < NBLK; b++) {
        k_qkv<<<dim3(L/16, 3), 256>>>(pQbuf, Wq + (size_t)b*CA*CA,
                                      Wk + (size_t)b*CA*CA, Wv + (size_t)b*CA*CA);
        k_attn_split<<<dim3(L/256, NH, KSPLIT), 128>>>(b);
        k_mlp<<<L/8, 256>>>(Wo + (size_t)b*CA*CA, Wt1 + (size_t)b*CA*FFDIM,
                            Wt2 + (size_t)b*FFDIM*CA);
    }

    k_out<<<dim3(L/16, 3), 256>>>(pQbuf, Wqtok, pFF, outQ);
    k_seg<<<TOKS, CT>>>(pFF, tok, outA);
}